// round 12
// baseline (speedup 1.0000x reference)
#include <cuda_runtime.h>
#include <cuda_fp16.h>
#include <math.h>
#include <stdint.h>

#define BB 4
#define TT 2048
#define CC 1024

// ---- scratch (static device globals; no allocs anywhere) --------------------
__device__ __align__(256) __half g_xh  [(size_t)BB * TT * CC];        // x in half
__device__ __align__(256) __half g_Wth [(size_t)3 * CC * CC];         // W^T [3C,C] half
__device__ __align__(256) __half g_qkvh[(size_t)BB * TT * 3 * CC];    // [B,T,3C] half
__device__ __align__(256) __half g_Sh  [(size_t)BB * TT * TT];        // scores half
__device__ __align__(256) __half g_Ph  [(size_t)BB * TT * TT];        // probs half

// ---- helpers ------------------------------------------------------------------
__device__ __forceinline__ uint32_t smem_u32(const void* p) {
    uint32_t a;
    asm("{ .reg .u64 t; cvta.to.shared.u64 t, %1; cvt.u32.u64 %0, t; }"
        : "=r"(a) : "l"(p));
    return a;
}
__device__ __forceinline__ void cp16(uint32_t dst, const void* src) {
    asm volatile("cp.async.cg.shared.global [%0], [%1], 16;"
                 :: "r"(dst), "l"(src) : "memory");
}
#define CP_COMMIT() asm volatile("cp.async.commit_group;" ::: "memory")
#define CP_WAIT(n)  asm volatile("cp.async.wait_group %0;" :: "n"(n) : "memory")

#define LDSM4(r, addr)                                                          \
    asm volatile("ldmatrix.sync.aligned.m8n8.x4.shared.b16 {%0,%1,%2,%3},[%4];" \
        : "=r"((r)[0]), "=r"((r)[1]), "=r"((r)[2]), "=r"((r)[3])                \
        : "r"(addr))

#define LDSM4T(r, addr)                                                         \
    asm volatile("ldmatrix.sync.aligned.m8n8.x4.trans.shared.b16 "              \
        "{%0,%1,%2,%3},[%4];"                                                   \
        : "=r"((r)[0]), "=r"((r)[1]), "=r"((r)[2]), "=r"((r)[3])                \
        : "r"(addr))

#define MMA16816(c, a, b0, b1)                                                  \
    asm volatile("mma.sync.aligned.m16n8k16.row.col.f32.f16.f16.f32 "           \
        "{%0,%1,%2,%3},{%4,%5,%6,%7},{%8,%9},{%0,%1,%2,%3};"                    \
        : "+f"((c)[0]), "+f"((c)[1]), "+f"((c)[2]), "+f"((c)[3])                 \
        : "r"((a)[0]), "r"((a)[1]), "r"((a)[2]), "r"((a)[3]),                    \
          "r"(b0), "r"(b1))

#define MMA16816H(c, a, b0, b1)                                                 \
    asm volatile("mma.sync.aligned.m16n8k16.row.col.f16.f16.f16.f16 "           \
        "{%0,%1},{%2,%3,%4,%5},{%6,%7},{%0,%1};"                                \
        : "+r"((c)[0]), "+r"((c)[1])                                            \
        : "r"((a)[0]), "r"((a)[1]), "r"((a)[2]), "r"((a)[3]),                    \
          "r"(b0), "r"(b1))

// ---- fp16 HMMA GEMM ------------------------------------------------------------
// BNN=false: C[M,N] = scale * A[M,K] * B[N,K]^T   (B row-major [N,K])
// BNN=true : C[M,N] = scale * A[M,K] * B[K,N]     (B row-major [K,N], ldmatrix.trans)
// TRI:  grid.x indexes the lower triangle of the (M/128 x M/128) tile grid.
// LIMK: truncate K at bm+128; blockIdx.y reversed so heavy tiles launch first.
// HACC: accumulate in fp16 (2 regs/fragment) — only safe where partial-sum
//       rounding stays inside the error budget (GEMM2 scores).
// 128x128 CTA tile, BK=32, 5-stage cp.async, 128 thr = 4 warps (2x2 of 64x64).
#define STAGES     5
#define ASTRIDE    80                 // A smem row: 64B data + 16B pad
#define AT_BYTES   (128 * ASTRIDE)    // 10240
#define BROWB_NN   272                // NN B smem row: 256B data + 16B pad (odd/16)

template <bool TRI, bool LIMK, bool OUTH, bool BNN, bool HACC>
__global__ void __launch_bounds__(128, 2)
gemm_hmma(const __half* __restrict__ A, const __half* __restrict__ B,
          void* __restrict__ Cout,
          int K, int lda, int ldb, int ldc,
          long sA, long sB, long sC, float scale)
{
    constexpr uint32_t B_BYTES = BNN ? (32u * BROWB_NN) : (128u * ASTRIDE);
    constexpr uint32_t STG_BYTES = AT_BYTES + B_BYTES;

    extern __shared__ char smem[];
    const int bz = blockIdx.z;
    A += (long)bz * sA;
    B += (long)bz * sB;

    int bm, bn;
    if (TRI) {
        const int idx = blockIdx.x;
        int r = (int)((sqrtf(8.0f * idx + 1.0f) - 1.0f) * 0.5f);
        while ((r + 1) * (r + 2) / 2 <= idx) ++r;
        while (r * (r + 1) / 2 > idx) --r;
        bm = r * 128;
        bn = (idx - r * (r + 1) / 2) * 128;
    } else if (LIMK) {
        bm = (gridDim.y - 1 - blockIdx.y) * 128;   // heavy tiles first
        bn = blockIdx.x * 128;
    } else {
        bm = blockIdx.y * 128;
        bn = blockIdx.x * 128;
    }

    const int kend = LIMK ? min(K, bm + 128) : K;
    const int nch  = kend >> 5;                         // 32-K chunks

    const int tid = threadIdx.x, lane = tid & 31, wid = tid >> 5;
    const int m0 = (wid >> 1) * 64, n0 = (wid & 1) * 64;
    const uint32_t sb = smem_u32(smem);

    float    accf[HACC ? 1 : 4][8][4];
    uint32_t acch[HACC ? 4 : 1][8][2];
    if constexpr (HACC) {
#pragma unroll
        for (int i = 0; i < 4; i++)
#pragma unroll
            for (int j = 0; j < 8; j++) { acch[i][j][0] = 0u; acch[i][j][1] = 0u; }
    } else {
#pragma unroll
        for (int i = 0; i < 4; i++)
#pragma unroll
            for (int j = 0; j < 8; j++)
#pragma unroll
                for (int q = 0; q < 4; q++) accf[i][j][q] = 0.0f;
    }

#define LOAD_STAGE(kt, s)                                                        \
    do {                                                                         \
        const __half* Ab_ = A + (size_t)bm * lda + (kt) * 32;                    \
        const uint32_t sa_ = sb + (uint32_t)(s) * STG_BYTES;                     \
        const uint32_t sbb_ = sa_ + AT_BYTES;                                    \
        _Pragma("unroll")                                                        \
        for (int i_ = 0; i_ < 4; i_++) {                                         \
            const int idx_ = tid + i_ * 128;                                     \
            const int r_ = idx_ >> 2, c_ = idx_ & 3;                             \
            cp16(sa_ + r_ * ASTRIDE + c_ * 16, Ab_ + (size_t)r_ * lda + c_ * 8); \
        }                                                                        \
        if (BNN) {                                                               \
            const __half* Bb_ = B + (size_t)(kt) * 32 * ldb + bn;                \
            _Pragma("unroll")                                                    \
            for (int i_ = 0; i_ < 4; i_++) {                                     \
                const int idx_ = tid + i_ * 128;                                 \
                const int r_ = idx_ >> 4, c_ = idx_ & 15;                        \
                cp16(sbb_ + r_ * BROWB_NN + c_ * 16,                             \
                     Bb_ + (size_t)r_ * ldb + c_ * 8);                           \
            }                                                                    \
        } else {                                                                 \
            const __half* Bb_ = B + (size_t)bn * ldb + (kt) * 32;                \
            _Pragma("unroll")                                                    \
            for (int i_ = 0; i_ < 4; i_++) {                                     \
                const int idx_ = tid + i_ * 128;                                 \
                const int r_ = idx_ >> 2, c_ = idx_ & 3;                         \
                cp16(sbb_ + r_ * ASTRIDE + c_ * 16,                              \
                     Bb_ + (size_t)r_ * ldb + c_ * 8);                           \
            }                                                                    \
        }                                                                        \
    } while (0)

    // prologue: fill STAGES-1 stages
#pragma unroll
    for (int s = 0; s < STAGES - 1; s++) {
        if (s < nch) LOAD_STAGE(s, s);
        CP_COMMIT();
    }

    int s_cur = 0;
    int s_load = STAGES - 1;

    for (int kt = 0; kt < nch; kt++) {
        CP_WAIT(STAGES - 2);
        __syncthreads();

        const int nk = kt + STAGES - 1;
        if (nk < nch) LOAD_STAGE(nk, s_load);
        CP_COMMIT();
        if (++s_load == STAGES) s_load = 0;

        const uint32_t sa  = sb + (uint32_t)s_cur * STG_BYTES;
        const uint32_t sbb = sa + AT_BYTES;
        if (++s_cur == STAGES) s_cur = 0;

        uint32_t a[2][4][4], b[4][4];

        // a-frags for BOTH k16 steps
#pragma unroll
        for (int ks = 0; ks < 2; ks++)
#pragma unroll
            for (int mf = 0; mf < 4; mf++) {
                const uint32_t addr = sa
                    + (m0 + mf * 16 + (lane & 15)) * ASTRIDE
                    + ks * 32 + ((lane >> 4) & 1) * 16;
                LDSM4(a[ks][mf], addr);
            }
        // b-frags ks=0
#pragma unroll
        for (int nb = 0; nb < 4; nb++) {
            if (BNN) {
                const uint32_t addr = sbb
                    + (lane & 15) * BROWB_NN
                    + (n0 + nb * 16 + ((lane >> 4) & 1) * 8) * 2;
                LDSM4T(b[nb], addr);
            } else {
                const uint32_t addr = sbb
                    + (n0 + nb * 16 + ((lane >> 4) & 1) * 8 + (lane & 7)) * ASTRIDE
                    + ((lane >> 3) & 1) * 16;
                LDSM4(b[nb], addr);
            }
        }
        // MMA ks=0
#pragma unroll
        for (int mf = 0; mf < 4; mf++)
#pragma unroll
            for (int nf = 0; nf < 8; nf++) {
                if constexpr (HACC)
                    MMA16816H(acch[mf][nf], a[0][mf],
                              b[nf >> 1][(nf & 1) * 2],
                              b[nf >> 1][(nf & 1) * 2 + 1]);
                else
                    MMA16816(accf[mf][nf], a[0][mf],
                             b[nf >> 1][(nf & 1) * 2],
                             b[nf >> 1][(nf & 1) * 2 + 1]);
            }
        // b-frags ks=1 (WAR overlap with ks=0 MMAs)
#pragma unroll
        for (int nb = 0; nb < 4; nb++) {
            if (BNN) {
                const uint32_t addr = sbb
                    + (16 + (lane & 15)) * BROWB_NN
                    + (n0 + nb * 16 + ((lane >> 4) & 1) * 8) * 2;
                LDSM4T(b[nb], addr);
            } else {
                const uint32_t addr = sbb
                    + (n0 + nb * 16 + ((lane >> 4) & 1) * 8 + (lane & 7)) * ASTRIDE
                    + 32 + ((lane >> 3) & 1) * 16;
                LDSM4(b[nb], addr);
            }
        }
        // MMA ks=1
#pragma unroll
        for (int mf = 0; mf < 4; mf++)
#pragma unroll
            for (int nf = 0; nf < 8; nf++) {
                if constexpr (HACC)
                    MMA16816H(acch[mf][nf], a[1][mf],
                              b[nf >> 1][(nf & 1) * 2],
                              b[nf >> 1][(nf & 1) * 2 + 1]);
                else
                    MMA16816(accf[mf][nf], a[1][mf],
                             b[nf >> 1][(nf & 1) * 2],
                             b[nf >> 1][(nf & 1) * 2 + 1]);
            }
    }

    // epilogue
    const int gr = lane >> 2, gc = (lane & 3) * 2;
#pragma unroll
    for (int mf = 0; mf < 4; mf++) {
        const int row = bm + m0 + mf * 16 + gr;
#pragma unroll
        for (int nf = 0; nf < 8; nf++) {
            const int col = bn + n0 + nf * 8 + gc;
            float v0, v1, v2, v3;
            if constexpr (HACC) {
                const __half2 h01 = *(const __half2*)&acch[mf][nf][0];
                const __half2 h23 = *(const __half2*)&acch[mf][nf][1];
                v0 = __half2float(h01.x) * scale;
                v1 = __half2float(h01.y) * scale;
                v2 = __half2float(h23.x) * scale;
                v3 = __half2float(h23.y) * scale;
            } else {
                v0 = accf[mf][nf][0] * scale;
                v1 = accf[mf][nf][1] * scale;
                v2 = accf[mf][nf][2] * scale;
                v3 = accf[mf][nf][3] * scale;
            }
            if (OUTH) {
                __half* Cp = (__half*)Cout + (long)bz * sC;
                *(__half2*)(Cp + (size_t)row * ldc + col) =
                    __floats2half2_rn(v0, v1);
                *(__half2*)(Cp + (size_t)(row + 8) * ldc + col) =
                    __floats2half2_rn(v2, v3);
            } else {
                float* Cp = (float*)Cout + (long)bz * sC;
                *(float2*)(Cp + (size_t)row * ldc + col) = make_float2(v0, v1);
                *(float2*)(Cp + (size_t)(row + 8) * ldc + col) = make_float2(v2, v3);
            }
        }
    }
#undef LOAD_STAGE
}

// ---- fp32 -> fp16 copy ---------------------------------------------------------
__global__ void cvt_half(const float* __restrict__ x, __half* __restrict__ xh, int n2)
{
    int i = blockIdx.x * blockDim.x + threadIdx.x;
    for (; i < n2; i += gridDim.x * blockDim.x) {
        float2 v = ((const float2*)x)[i];
        ((__half2*)xh)[i] = __floats2half2_rn(v.x, v.y);
    }
}

// ---- W^T (fp32 in, half out) ----------------------------------------------------
__global__ void transposeW(const float* __restrict__ W, __half* __restrict__ Wt)
{
    __shared__ float t[32][33];
    const int d0 = blockIdx.x * 32, c0 = blockIdx.y * 32;
    const int x = threadIdx.x, y = threadIdx.y;
#pragma unroll
    for (int i = 0; i < 32; i += 8)
        t[y + i][x] = W[(size_t)(c0 + y + i) * (3 * CC) + d0 + x];
    __syncthreads();
#pragma unroll
    for (int i = 0; i < 32; i += 8)
        Wt[(size_t)(d0 + y + i) * CC + c0 + x] = __float2half_rn(t[x][y + i]);
}

// ---- causal softmax: register-cached single pass. S half in, P half out. --------
__global__ void softmax_causal(const __half* __restrict__ S, __half* __restrict__ P)
{
    const int row = blockIdx.x;            // 0 .. B*T-1
    const int b = row / TT;
    const int i = row % TT;
    const __half* Srow = S + (size_t)b * TT * TT + (size_t)i * TT;
    __half* Prow = P + (size_t)b * TT * TT + (size_t)i * TT;
    const int len = i + 1;
    const int fillend = ((i >> 7) + 1) << 7;   // next 128 multiple
    const int t = threadIdx.x;

    __shared__ float sh[8];

    float r[8];
    int cnt = 0;
    float mx = -INFINITY;
#pragma unroll
    for (int q = 0; q < 8; q++) {
        const int j = t + q * 256;
        if (j < len) {
            r[q] = __half2float(Srow[j]);
            mx = fmaxf(mx, r[q]);
            cnt = q + 1;
        }
    }
#pragma unroll
    for (int o = 16; o; o >>= 1) mx = fmaxf(mx, __shfl_xor_sync(0xffffffffu, mx, o));
    if ((t & 31) == 0) sh[t >> 5] = mx;
    __syncthreads();
    mx = sh[0];
#pragma unroll
    for (int w = 1; w < 8; w++) mx = fmaxf(mx, sh[w]);
    __syncthreads();

    float sum = 0.0f;
#pragma unroll
    for (int q = 0; q < 8; q++) {
        if (q < cnt) {
            r[q] = __expf(r[q] - mx);
            sum += r[q];
        }
    }
#pragma unroll
    for (int o = 16; o; o >>= 1) sum += __shfl_xor_sync(0xffffffffu, sum, o);
    if ((t & 31) == 0) sh[t >> 5] = sum;
    __syncthreads();
    sum = sh[0];
#pragma unroll
    for (int w = 1; w < 8; w++) sum += sh[w];

    const float inv = 1.0f / sum;
#pragma unroll
    for (int q = 0; q < 8; q++) {
        const int j = t + q * 256;
        if (j < len) Prow[j] = __float2half_rn(r[q] * inv);
    }
    const __half hz = __float2half_rn(0.0f);
    for (int j = len + t; j < fillend; j += 256) Prow[j] = hz;
}

// ---- launch -----------------------------------------------------------------------
#define SMEM_NT (STAGES * (AT_BYTES + 128 * ASTRIDE))   // 102400
#define SMEM_NN (STAGES * (AT_BYTES + 32 * BROWB_NN))   // 94720

extern "C" void kernel_launch(void* const* d_in, const int* in_sizes, int n_in,
                              void* d_out, int out_size)
{
    const float* x = (const float*)d_in[0];   // [B,T,C]
    const float* W = (const float*)d_in[1];   // [C,3C]
    float* out = (float*)d_out;               // [B,T,C]

    __half *xh, *Wth, *qkvh, *Sh, *Ph;
    cudaGetSymbolAddress((void**)&xh,   g_xh);
    cudaGetSymbolAddress((void**)&Wth,  g_Wth);
    cudaGetSymbolAddress((void**)&qkvh, g_qkvh);
    cudaGetSymbolAddress((void**)&Sh,   g_Sh);
    cudaGetSymbolAddress((void**)&Ph,   g_Ph);

    cudaFuncSetAttribute(gemm_hmma<false, false, true, false, false>,
                         cudaFuncAttributeMaxDynamicSharedMemorySize, SMEM_NT);
    cudaFuncSetAttribute(gemm_hmma<true, false, true, false, true>,
                         cudaFuncAttributeMaxDynamicSharedMemorySize, SMEM_NT);
    cudaFuncSetAttribute(gemm_hmma<false, true, false, true, false>,
                         cudaFuncAttributeMaxDynamicSharedMemorySize, SMEM_NN);

    cudaStream_t st1;
    cudaStreamCreateWithFlags(&st1, cudaStreamNonBlocking);
    cudaEvent_t evFork, evW, evX2, evQK, evV;
    cudaEventCreateWithFlags(&evFork, cudaEventDisableTiming);
    cudaEventCreateWithFlags(&evW,    cudaEventDisableTiming);
    cudaEventCreateWithFlags(&evX2,   cudaEventDisableTiming);
    cudaEventCreateWithFlags(&evQK,   cudaEventDisableTiming);
    cudaEventCreateWithFlags(&evV,    cudaEventDisableTiming);

    // FORK st1 off the capture (origin) stream before any work lands on it.
    cudaEventRecord(evFork, 0);
    cudaStreamWaitEvent(st1, evFork, 0);

    const int half_elems2 = BB * TT * CC / 4;   // float2 count for 2 batches

    // prep: cvt batches 0-1 on origin; W^T then cvt batches 2-3 on st1
    cvt_half<<<1024, 256>>>(x, xh, half_elems2);
    transposeW<<<dim3(3 * CC / 32, CC / 32), dim3(32, 8), 0, st1>>>(W, Wth);
    cudaEventRecord(evW, st1);
    cvt_half<<<1024, 256, 0, st1>>>(x + (size_t)2 * TT * CC,
                                    xh + (size_t)2 * TT * CC, half_elems2);
    cudaEventRecord(evX2, st1);

    // 1a) QK projection, batches 0-1 (origin; needs cvt01 + W)
    cudaStreamWaitEvent(0, evW, 0);
    gemm_hmma<false, false, true, false, false>
        <<<dim3(2 * CC / 128, 2 * TT / 128, 1), 128, SMEM_NT>>>(
        xh, Wth, qkvh, CC, CC, CC, 3 * CC, 0, 0, 0, 1.0f);

    // 1b) QK projection, batches 2-3 (origin; needs cvt23)
    cudaStreamWaitEvent(0, evX2, 0);
    gemm_hmma<false, false, true, false, false>
        <<<dim3(2 * CC / 128, 2 * TT / 128, 1), 128, SMEM_NT>>>(
        xh + (size_t)2 * TT * CC, Wth, qkvh + (size_t)2 * TT * 3 * CC,
        CC, CC, CC, 3 * CC, 0, 0, 0, 1.0f);
    cudaEventRecord(evQK, 0);

    // 1c) V projection, all batches, on st1 AFTER qk (overlaps GEMM2+softmax tails)
    cudaStreamWaitEvent(st1, evQK, 0);
    gemm_hmma<false, false, true, false, false>
        <<<dim3(CC / 128, BB * TT / 128, 1), 128, SMEM_NT, st1>>>(
        xh, Wth + (size_t)2 * CC * CC, qkvh + 2 * CC,
        CC, CC, CC, 3 * CC, 0, 0, 0, 1.0f);
    cudaEventRecord(evV, st1);

    // 2) Sh = Q K^T / 32, all batches, triangular-compact, fp16 accumulate
    gemm_hmma<true, false, true, false, true>
        <<<dim3(136, 1, BB), 128, SMEM_NT>>>(
        qkvh, qkvh + CC, Sh, CC, 3 * CC, 3 * CC, TT,
        (long)TT * 3 * CC, (long)TT * 3 * CC, (long)TT * TT, 0.03125f);

    // 3) causal softmax -> Ph
    softmax_causal<<<BB * TT, 256>>>(Sh, Ph);

    // 4) out = P V (needs V): join st1, NN GEMM, heavy tiles first, fp32 acc
    cudaStreamWaitEvent(0, evV, 0);
    gemm_hmma<false, true, false, true, false>
        <<<dim3(CC / 128, TT / 128, BB), 128, SMEM_NN>>>(
        Ph, qkvh + 2 * CC, out, TT, TT, 3 * CC, CC,
        (long)TT * TT, (long)TT * 3 * CC, (long)TT * CC, 1.0f);

    cudaEventDestroy(evFork);
    cudaEventDestroy(evW);
    cudaEventDestroy(evX2);
    cudaEventDestroy(evQK);
    cudaEventDestroy(evV);
    cudaStreamDestroy(st1);
}

// round 13
// speedup vs baseline: 1.0111x; 1.0111x over previous
#include <cuda_runtime.h>
#include <cuda_fp16.h>
#include <math.h>
#include <stdint.h>

#define BB 4
#define TT 2048
#define CC 1024

// ---- scratch (static device globals; no allocs anywhere) --------------------
__device__ __align__(256) __half g_xh  [(size_t)BB * TT * CC];        // x in half
__device__ __align__(256) __half g_Wth [(size_t)3 * CC * CC];         // W^T [3C,C] half
__device__ __align__(256) __half g_qkvh[(size_t)BB * TT * 3 * CC];    // [B,T,3C] half
__device__ __align__(256) __half g_Sh  [(size_t)BB * TT * TT];        // scores half
__device__ __align__(256) __half g_Ph  [(size_t)BB * TT * TT];        // probs half

// ---- helpers ------------------------------------------------------------------
__device__ __forceinline__ uint32_t smem_u32(const void* p) {
    uint32_t a;
    asm("{ .reg .u64 t; cvta.to.shared.u64 t, %1; cvt.u32.u64 %0, t; }"
        : "=r"(a) : "l"(p));
    return a;
}
__device__ __forceinline__ void cp16(uint32_t dst, const void* src) {
    asm volatile("cp.async.cg.shared.global [%0], [%1], 16;"
                 :: "r"(dst), "l"(src) : "memory");
}
#define CP_COMMIT() asm volatile("cp.async.commit_group;" ::: "memory")
#define CP_WAIT(n)  asm volatile("cp.async.wait_group %0;" :: "n"(n) : "memory")

#define LDSM4(r, addr)                                                          \
    asm volatile("ldmatrix.sync.aligned.m8n8.x4.shared.b16 {%0,%1,%2,%3},[%4];" \
        : "=r"((r)[0]), "=r"((r)[1]), "=r"((r)[2]), "=r"((r)[3])                \
        : "r"(addr))

#define LDSM4T(r, addr)                                                         \
    asm volatile("ldmatrix.sync.aligned.m8n8.x4.trans.shared.b16 "              \
        "{%0,%1,%2,%3},[%4];"                                                   \
        : "=r"((r)[0]), "=r"((r)[1]), "=r"((r)[2]), "=r"((r)[3])                \
        : "r"(addr))

#define MMA16816(c, a, b0, b1)                                                  \
    asm volatile("mma.sync.aligned.m16n8k16.row.col.f32.f16.f16.f32 "           \
        "{%0,%1,%2,%3},{%4,%5,%6,%7},{%8,%9},{%0,%1,%2,%3};"                    \
        : "+f"((c)[0]), "+f"((c)[1]), "+f"((c)[2]), "+f"((c)[3])                 \
        : "r"((a)[0]), "r"((a)[1]), "r"((a)[2]), "r"((a)[3]),                    \
          "r"(b0), "r"(b1))

#define MMA16816H(c, a, b0, b1)                                                 \
    asm volatile("mma.sync.aligned.m16n8k16.row.col.f16.f16.f16.f16 "           \
        "{%0,%1},{%2,%3,%4,%5},{%6,%7},{%0,%1};"                                \
        : "+r"((c)[0]), "+r"((c)[1])                                            \
        : "r"((a)[0]), "r"((a)[1]), "r"((a)[2]), "r"((a)[3]),                    \
          "r"(b0), "r"(b1))

// ---- fp16 HMMA GEMM ------------------------------------------------------------
// BNN=false: C[M,N] = scale * A[M,K] * B[N,K]^T   (B row-major [N,K])
// BNN=true : C[M,N] = scale * A[M,K] * B[K,N]     (B row-major [K,N], ldmatrix.trans)
// TRI:  grid.x indexes the lower triangle of the (M/128 x M/128) tile grid.
// LIMK: truncate K at bm+128; blockIdx.y reversed so heavy tiles launch first.
// HACC: fp16 accumulation (GEMM2 scores only — error budget verified in R12).
// 128x128 CTA tile, BK=32, 5-stage cp.async, 128 thr = 4 warps (2x2 of 64x64).
#define STAGES     5
#define ASTRIDE    80                 // A smem row: 64B data + 16B pad
#define AT_BYTES   (128 * ASTRIDE)    // 10240
#define BROWB_NN   272                // NN B smem row: 256B data + 16B pad (odd/16)

template <bool TRI, bool LIMK, bool OUTH, bool BNN, bool HACC>
__global__ void __launch_bounds__(128, 2)
gemm_hmma(const __half* __restrict__ A, const __half* __restrict__ B,
          void* __restrict__ Cout,
          int K, int lda, int ldb, int ldc,
          long sA, long sB, long sC, float scale)
{
    constexpr uint32_t B_BYTES = BNN ? (32u * BROWB_NN) : (128u * ASTRIDE);
    constexpr uint32_t STG_BYTES = AT_BYTES + B_BYTES;

    extern __shared__ char smem[];
    const int bz = blockIdx.z;
    A += (long)bz * sA;
    B += (long)bz * sB;

    int bm, bn;
    if (TRI) {
        const int idx = blockIdx.x;
        int r = (int)((sqrtf(8.0f * idx + 1.0f) - 1.0f) * 0.5f);
        while ((r + 1) * (r + 2) / 2 <= idx) ++r;
        while (r * (r + 1) / 2 > idx) --r;
        bm = r * 128;
        bn = (idx - r * (r + 1) / 2) * 128;
    } else if (LIMK) {
        bm = (gridDim.y - 1 - blockIdx.y) * 128;   // heavy tiles first
        bn = blockIdx.x * 128;
    } else {
        bm = blockIdx.y * 128;
        bn = blockIdx.x * 128;
    }

    const int kend = LIMK ? min(K, bm + 128) : K;
    const int nch  = kend >> 5;                         // 32-K chunks

    const int tid = threadIdx.x, lane = tid & 31, wid = tid >> 5;
    const int m0 = (wid >> 1) * 64, n0 = (wid & 1) * 64;
    const uint32_t sb = smem_u32(smem);

    float    accf[HACC ? 1 : 4][8][4];
    uint32_t acch[HACC ? 4 : 1][8][2];
    if constexpr (HACC) {
#pragma unroll
        for (int i = 0; i < 4; i++)
#pragma unroll
            for (int j = 0; j < 8; j++) { acch[i][j][0] = 0u; acch[i][j][1] = 0u; }
    } else {
#pragma unroll
        for (int i = 0; i < 4; i++)
#pragma unroll
            for (int j = 0; j < 8; j++)
#pragma unroll
                for (int q = 0; q < 4; q++) accf[i][j][q] = 0.0f;
    }

#define LOAD_STAGE(kt, s)                                                        \
    do {                                                                         \
        const __half* Ab_ = A + (size_t)bm * lda + (kt) * 32;                    \
        const uint32_t sa_ = sb + (uint32_t)(s) * STG_BYTES;                     \
        const uint32_t sbb_ = sa_ + AT_BYTES;                                    \
        _Pragma("unroll")                                                        \
        for (int i_ = 0; i_ < 4; i_++) {                                         \
            const int idx_ = tid + i_ * 128;                                     \
            const int r_ = idx_ >> 2, c_ = idx_ & 3;                             \
            cp16(sa_ + r_ * ASTRIDE + c_ * 16, Ab_ + (size_t)r_ * lda + c_ * 8); \
        }                                                                        \
        if (BNN) {                                                               \
            const __half* Bb_ = B + (size_t)(kt) * 32 * ldb + bn;                \
            _Pragma("unroll")                                                    \
            for (int i_ = 0; i_ < 4; i_++) {                                     \
                const int idx_ = tid + i_ * 128;                                 \
                const int r_ = idx_ >> 4, c_ = idx_ & 15;                        \
                cp16(sbb_ + r_ * BROWB_NN + c_ * 16,                             \
                     Bb_ + (size_t)r_ * ldb + c_ * 8);                           \
            }                                                                    \
        } else {                                                                 \
            const __half* Bb_ = B + (size_t)bn * ldb + (kt) * 32;                \
            _Pragma("unroll")                                                    \
            for (int i_ = 0; i_ < 4; i_++) {                                     \
                const int idx_ = tid + i_ * 128;                                 \
                const int r_ = idx_ >> 2, c_ = idx_ & 3;                         \
                cp16(sbb_ + r_ * ASTRIDE + c_ * 16,                              \
                     Bb_ + (size_t)r_ * ldb + c_ * 8);                           \
            }                                                                    \
        }                                                                        \
    } while (0)

    // prologue: fill STAGES-1 stages
#pragma unroll
    for (int s = 0; s < STAGES - 1; s++) {
        if (s < nch) LOAD_STAGE(s, s);
        CP_COMMIT();
    }

    int s_cur = 0;
    int s_load = STAGES - 1;

    for (int kt = 0; kt < nch; kt++) {
        CP_WAIT(STAGES - 2);
        __syncthreads();

        const int nk = kt + STAGES - 1;
        if (nk < nch) LOAD_STAGE(nk, s_load);
        CP_COMMIT();
        if (++s_load == STAGES) s_load = 0;

        const uint32_t sa  = sb + (uint32_t)s_cur * STG_BYTES;
        const uint32_t sbb = sa + AT_BYTES;
        if (++s_cur == STAGES) s_cur = 0;

        uint32_t a[2][4][4], b[4][4];

        // a-frags for BOTH k16 steps
#pragma unroll
        for (int ks = 0; ks < 2; ks++)
#pragma unroll
            for (int mf = 0; mf < 4; mf++) {
                const uint32_t addr = sa
                    + (m0 + mf * 16 + (lane & 15)) * ASTRIDE
                    + ks * 32 + ((lane >> 4) & 1) * 16;
                LDSM4(a[ks][mf], addr);
            }
        // b-frags ks=0
#pragma unroll
        for (int nb = 0; nb < 4; nb++) {
            if (BNN) {
                const uint32_t addr = sbb
                    + (lane & 15) * BROWB_NN
                    + (n0 + nb * 16 + ((lane >> 4) & 1) * 8) * 2;
                LDSM4T(b[nb], addr);
            } else {
                const uint32_t addr = sbb
                    + (n0 + nb * 16 + ((lane >> 4) & 1) * 8 + (lane & 7)) * ASTRIDE
                    + ((lane >> 3) & 1) * 16;
                LDSM4(b[nb], addr);
            }
        }
        // MMA ks=0
#pragma unroll
        for (int mf = 0; mf < 4; mf++)
#pragma unroll
            for (int nf = 0; nf < 8; nf++) {
                if constexpr (HACC)
                    MMA16816H(acch[mf][nf], a[0][mf],
                              b[nf >> 1][(nf & 1) * 2],
                              b[nf >> 1][(nf & 1) * 2 + 1]);
                else
                    MMA16816(accf[mf][nf], a[0][mf],
                             b[nf >> 1][(nf & 1) * 2],
                             b[nf >> 1][(nf & 1) * 2 + 1]);
            }
        // b-frags ks=1 (WAR overlap with ks=0 MMAs)
#pragma unroll
        for (int nb = 0; nb < 4; nb++) {
            if (BNN) {
                const uint32_t addr = sbb
                    + (16 + (lane & 15)) * BROWB_NN
                    + (n0 + nb * 16 + ((lane >> 4) & 1) * 8) * 2;
                LDSM4T(b[nb], addr);
            } else {
                const uint32_t addr = sbb
                    + (n0 + nb * 16 + ((lane >> 4) & 1) * 8 + (lane & 7)) * ASTRIDE
                    + 32 + ((lane >> 3) & 1) * 16;
                LDSM4(b[nb], addr);
            }
        }
        // MMA ks=1
#pragma unroll
        for (int mf = 0; mf < 4; mf++)
#pragma unroll
            for (int nf = 0; nf < 8; nf++) {
                if constexpr (HACC)
                    MMA16816H(acch[mf][nf], a[1][mf],
                              b[nf >> 1][(nf & 1) * 2],
                              b[nf >> 1][(nf & 1) * 2 + 1]);
                else
                    MMA16816(accf[mf][nf], a[1][mf],
                             b[nf >> 1][(nf & 1) * 2],
                             b[nf >> 1][(nf & 1) * 2 + 1]);
            }
    }

    // epilogue
    const int gr = lane >> 2, gc = (lane & 3) * 2;
#pragma unroll
    for (int mf = 0; mf < 4; mf++) {
        const int row = bm + m0 + mf * 16 + gr;
#pragma unroll
        for (int nf = 0; nf < 8; nf++) {
            const int col = bn + n0 + nf * 8 + gc;
            float v0, v1, v2, v3;
            if constexpr (HACC) {
                const __half2 h01 = *(const __half2*)&acch[mf][nf][0];
                const __half2 h23 = *(const __half2*)&acch[mf][nf][1];
                v0 = __half2float(h01.x) * scale;
                v1 = __half2float(h01.y) * scale;
                v2 = __half2float(h23.x) * scale;
                v3 = __half2float(h23.y) * scale;
            } else {
                v0 = accf[mf][nf][0] * scale;
                v1 = accf[mf][nf][1] * scale;
                v2 = accf[mf][nf][2] * scale;
                v3 = accf[mf][nf][3] * scale;
            }
            if (OUTH) {
                __half* Cp = (__half*)Cout + (long)bz * sC;
                *(__half2*)(Cp + (size_t)row * ldc + col) =
                    __floats2half2_rn(v0, v1);
                *(__half2*)(Cp + (size_t)(row + 8) * ldc + col) =
                    __floats2half2_rn(v2, v3);
            } else {
                float* Cp = (float*)Cout + (long)bz * sC;
                *(float2*)(Cp + (size_t)row * ldc + col) = make_float2(v0, v1);
                *(float2*)(Cp + (size_t)(row + 8) * ldc + col) = make_float2(v2, v3);
            }
        }
    }
#undef LOAD_STAGE
}

// ---- fp32 -> fp16 copy ---------------------------------------------------------
__global__ void cvt_half(const float* __restrict__ x, __half* __restrict__ xh, int n2)
{
    int i = blockIdx.x * blockDim.x + threadIdx.x;
    for (; i < n2; i += gridDim.x * blockDim.x) {
        float2 v = ((const float2*)x)[i];
        ((__half2*)xh)[i] = __floats2half2_rn(v.x, v.y);
    }
}

// ---- W^T (fp32 in, half out) ----------------------------------------------------
__global__ void transposeW(const float* __restrict__ W, __half* __restrict__ Wt)
{
    __shared__ float t[32][33];
    const int d0 = blockIdx.x * 32, c0 = blockIdx.y * 32;
    const int x = threadIdx.x, y = threadIdx.y;
#pragma unroll
    for (int i = 0; i < 32; i += 8)
        t[y + i][x] = W[(size_t)(c0 + y + i) * (3 * CC) + d0 + x];
    __syncthreads();
#pragma unroll
    for (int i = 0; i < 32; i += 8)
        Wt[(size_t)(d0 + y + i) * CC + c0 + x] = __float2half_rn(t[x][y + i]);
}

// ---- causal softmax: register-cached single pass. S half in, P half out. --------
__global__ void softmax_causal(const __half* __restrict__ S, __half* __restrict__ P)
{
    const int row = blockIdx.x;            // 0 .. B*T-1
    const int b = row / TT;
    const int i = row % TT;
    const __half* Srow = S + (size_t)b * TT * TT + (size_t)i * TT;
    __half* Prow = P + (size_t)b * TT * TT + (size_t)i * TT;
    const int len = i + 1;
    const int fillend = ((i >> 7) + 1) << 7;   // next 128 multiple
    const int t = threadIdx.x;

    __shared__ float sh[8];

    float r[8];
    int cnt = 0;
    float mx = -INFINITY;
#pragma unroll
    for (int q = 0; q < 8; q++) {
        const int j = t + q * 256;
        if (j < len) {
            r[q] = __half2float(Srow[j]);
            mx = fmaxf(mx, r[q]);
            cnt = q + 1;
        }
    }
#pragma unroll
    for (int o = 16; o; o >>= 1) mx = fmaxf(mx, __shfl_xor_sync(0xffffffffu, mx, o));
    if ((t & 31) == 0) sh[t >> 5] = mx;
    __syncthreads();
    mx = sh[0];
#pragma unroll
    for (int w = 1; w < 8; w++) mx = fmaxf(mx, sh[w]);
    __syncthreads();

    float sum = 0.0f;
#pragma unroll
    for (int q = 0; q < 8; q++) {
        if (q < cnt) {
            r[q] = __expf(r[q] - mx);
            sum += r[q];
        }
    }
#pragma unroll
    for (int o = 16; o; o >>= 1) sum += __shfl_xor_sync(0xffffffffu, sum, o);
    if ((t & 31) == 0) sh[t >> 5] = sum;
    __syncthreads();
    sum = sh[0];
#pragma unroll
    for (int w = 1; w < 8; w++) sum += sh[w];

    const float inv = 1.0f / sum;
#pragma unroll
    for (int q = 0; q < 8; q++) {
        const int j = t + q * 256;
        if (j < len) Prow[j] = __float2half_rn(r[q] * inv);
    }
    const __half hz = __float2half_rn(0.0f);
    for (int j = len + t; j < fillend; j += 256) Prow[j] = hz;
}

// ---- launch -----------------------------------------------------------------------
#define SMEM_NT (STAGES * (AT_BYTES + 128 * ASTRIDE))   // 102400
#define SMEM_NN (STAGES * (AT_BYTES + 32 * BROWB_NN))   // 94720

extern "C" void kernel_launch(void* const* d_in, const int* in_sizes, int n_in,
                              void* d_out, int out_size)
{
    const float* x = (const float*)d_in[0];   // [B,T,C]
    const float* W = (const float*)d_in[1];   // [C,3C]
    float* out = (float*)d_out;               // [B,T,C]

    __half *xh, *Wth, *qkvh, *Sh, *Ph;
    cudaGetSymbolAddress((void**)&xh,   g_xh);
    cudaGetSymbolAddress((void**)&Wth,  g_Wth);
    cudaGetSymbolAddress((void**)&qkvh, g_qkvh);
    cudaGetSymbolAddress((void**)&Sh,   g_Sh);
    cudaGetSymbolAddress((void**)&Ph,   g_Ph);

    cudaFuncSetAttribute(gemm_hmma<false, false, true, false, false>,
                         cudaFuncAttributeMaxDynamicSharedMemorySize, SMEM_NT);
    cudaFuncSetAttribute(gemm_hmma<true, false, true, false, true>,
                         cudaFuncAttributeMaxDynamicSharedMemorySize, SMEM_NT);
    cudaFuncSetAttribute(gemm_hmma<false, true, false, true, false>,
                         cudaFuncAttributeMaxDynamicSharedMemorySize, SMEM_NN);

    cudaStream_t st1;
    cudaStreamCreateWithFlags(&st1, cudaStreamNonBlocking);
    cudaEvent_t evFork, evW, evQK, evV;
    cudaEventCreateWithFlags(&evFork, cudaEventDisableTiming);
    cudaEventCreateWithFlags(&evW,    cudaEventDisableTiming);
    cudaEventCreateWithFlags(&evQK,   cudaEventDisableTiming);
    cudaEventCreateWithFlags(&evV,    cudaEventDisableTiming);

    // FORK st1 off the capture (origin) stream before any work lands on it.
    cudaEventRecord(evFork, 0);
    cudaStreamWaitEvent(st1, evFork, 0);

    // prep: cvt on origin, transposeW on st1 (overlap) — R11 schedule
    cvt_half<<<1024, 256>>>(x, xh, BB * TT * CC / 2);
    transposeW<<<dim3(3 * CC / 32, CC / 32), dim3(32, 8), 0, st1>>>(W, Wth);
    cudaEventRecord(evW, st1);

    // 1a) QK part of qkv: N = 2C (origin)
    cudaStreamWaitEvent(0, evW, 0);
    gemm_hmma<false, false, true, false, false>
        <<<dim3(2 * CC / 128, BB * TT / 128, 1), 128, SMEM_NT>>>(
        xh, Wth, qkvh, CC, CC, CC, 3 * CC, 0, 0, 0, 1.0f);
    cudaEventRecord(evQK, 0);

    // 1b) V part of qkv: N = C, on st1, after GEMM1qk (overlaps GEMM2+softmax)
    cudaStreamWaitEvent(st1, evQK, 0);
    gemm_hmma<false, false, true, false, false>
        <<<dim3(CC / 128, BB * TT / 128, 1), 128, SMEM_NT, st1>>>(
        xh, Wth + (size_t)2 * CC * CC, qkvh + 2 * CC,
        CC, CC, CC, 3 * CC, 0, 0, 0, 1.0f);
    cudaEventRecord(evV, st1);

    // 2) Sh = Q K^T / 32, all batches, triangular-compact, fp16 ACCUMULATE
    gemm_hmma<true, false, true, false, true>
        <<<dim3(136, 1, BB), 128, SMEM_NT>>>(
        qkvh, qkvh + CC, Sh, CC, 3 * CC, 3 * CC, TT,
        (long)TT * 3 * CC, (long)TT * 3 * CC, (long)TT * TT, 0.03125f);

    // 3) causal softmax -> Ph
    softmax_causal<<<BB * TT, 256>>>(Sh, Ph);

    // 4) out = P V (needs V): join st1, NN GEMM, heavy tiles first, fp32 acc
    cudaStreamWaitEvent(0, evV, 0);
    gemm_hmma<false, true, false, true, false>
        <<<dim3(CC / 128, TT / 128, BB), 128, SMEM_NN>>>(
        Ph, qkvh + 2 * CC, out, TT, TT, 3 * CC, CC,
        (long)TT * TT, (long)TT * 3 * CC, (long)TT * CC, 1.0f);

    cudaEventDestroy(evFork);
    cudaEventDestroy(evW);
    cudaEventDestroy(evQK);
    cudaEventDestroy(evV);
    cudaStreamDestroy(st1);
}

// round 14
// speedup vs baseline: 1.0242x; 1.0129x over previous
#include <cuda_runtime.h>
#include <cuda_fp16.h>
#include <math.h>
#include <stdint.h>

#define BB 4
#define TT 2048
#define CC 1024

// ---- scratch (static device globals; no allocs anywhere) --------------------
__device__ __align__(256) __half g_xh  [(size_t)BB * TT * CC];        // x in half
__device__ __align__(256) __half g_Wth [(size_t)3 * CC * CC];         // W^T [3C,C] half
__device__ __align__(256) __half g_qkvh[(size_t)BB * TT * 3 * CC];    // [B,T,3C] half
__device__ __align__(256) __half g_Sh  [(size_t)BB * TT * TT];        // scores half
__device__ __align__(256) __half g_Ph  [(size_t)BB * TT * TT];        // probs half

// ---- helpers ------------------------------------------------------------------
__device__ __forceinline__ uint32_t smem_u32(const void* p) {
    uint32_t a;
    asm("{ .reg .u64 t; cvta.to.shared.u64 t, %1; cvt.u32.u64 %0, t; }"
        : "=r"(a) : "l"(p));
    return a;
}
__device__ __forceinline__ void cp16(uint32_t dst, const void* src) {
    asm volatile("cp.async.cg.shared.global [%0], [%1], 16;"
                 :: "r"(dst), "l"(src) : "memory");
}
#define CP_COMMIT() asm volatile("cp.async.commit_group;" ::: "memory")
#define CP_WAIT(n)  asm volatile("cp.async.wait_group %0;" :: "n"(n) : "memory")

#define LDSM4(r, addr)                                                          \
    asm volatile("ldmatrix.sync.aligned.m8n8.x4.shared.b16 {%0,%1,%2,%3},[%4];" \
        : "=r"((r)[0]), "=r"((r)[1]), "=r"((r)[2]), "=r"((r)[3])                \
        : "r"(addr))

#define LDSM4T(r, addr)                                                         \
    asm volatile("ldmatrix.sync.aligned.m8n8.x4.trans.shared.b16 "              \
        "{%0,%1,%2,%3},[%4];"                                                   \
        : "=r"((r)[0]), "=r"((r)[1]), "=r"((r)[2]), "=r"((r)[3])                \
        : "r"(addr))

#define MMA16816(c, a, b0, b1)                                                  \
    asm volatile("mma.sync.aligned.m16n8k16.row.col.f32.f16.f16.f32 "           \
        "{%0,%1,%2,%3},{%4,%5,%6,%7},{%8,%9},{%0,%1,%2,%3};"                    \
        : "+f"((c)[0]), "+f"((c)[1]), "+f"((c)[2]), "+f"((c)[3])                 \
        : "r"((a)[0]), "r"((a)[1]), "r"((a)[2]), "r"((a)[3]),                    \
          "r"(b0), "r"(b1))

// ---- fp16 HMMA GEMM ------------------------------------------------------------
// BNN=false: C[M,N] = scale * A[M,K] * B[N,K]^T   (B row-major [N,K])
// BNN=true : C[M,N] = scale * A[M,K] * B[K,N]     (B row-major [K,N], ldmatrix.trans)
// TRI:  grid.x indexes the lower triangle of the (M/128 x M/128) tile grid;
//       on diagonal tiles the fully-masked upper-right 64x64 warp quadrant
//       skips its fragment loads / MMAs / stores (still syncs + stage-loads).
// LIMK: truncate K at bm+128; blockIdx.y reversed so heavy tiles launch first.
// 128x128 CTA tile, BK=32, 5-stage cp.async, 128 thr = 4 warps (2x2 of 64x64).
#define STAGES     5
#define ASTRIDE    80                 // A smem row: 64B data + 16B pad
#define AT_BYTES   (128 * ASTRIDE)    // 10240
#define BROWB_NN   272                // NN B smem row: 256B data + 16B pad (odd/16)

template <bool TRI, bool LIMK, bool OUTH, bool BNN>
__global__ void __launch_bounds__(128, 2)
gemm_hmma(const __half* __restrict__ A, const __half* __restrict__ B,
          void* __restrict__ Cout,
          int K, int lda, int ldb, int ldc,
          long sA, long sB, long sC, float scale)
{
    constexpr uint32_t B_BYTES = BNN ? (32u * BROWB_NN) : (128u * ASTRIDE);
    constexpr uint32_t STG_BYTES = AT_BYTES + B_BYTES;

    extern __shared__ char smem[];
    const int bz = blockIdx.z;
    A += (long)bz * sA;
    B += (long)bz * sB;

    int bm, bn;
    if (TRI) {
        const int idx = blockIdx.x;
        int r = (int)((sqrtf(8.0f * idx + 1.0f) - 1.0f) * 0.5f);
        while ((r + 1) * (r + 2) / 2 <= idx) ++r;
        while (r * (r + 1) / 2 > idx) --r;
        bm = r * 128;
        bn = (idx - r * (r + 1) / 2) * 128;
    } else if (LIMK) {
        bm = (gridDim.y - 1 - blockIdx.y) * 128;   // heavy tiles first
        bn = blockIdx.x * 128;
    } else {
        bm = blockIdx.y * 128;
        bn = blockIdx.x * 128;
    }

    const int kend = LIMK ? min(K, bm + 128) : K;
    const int nch  = kend >> 5;                         // 32-K chunks

    const int tid = threadIdx.x, lane = tid & 31, wid = tid >> 5;
    const int m0 = (wid >> 1) * 64, n0 = (wid & 1) * 64;
    const uint32_t sb = smem_u32(smem);

    // diagonal tile: upper-right 64x64 quadrant entirely above the causal
    // diagonal — never read downstream. Skip that warp's compute.
    const bool dead = TRI && (bm == bn) && (n0 > m0);

    float acc[4][8][4];
#pragma unroll
    for (int i = 0; i < 4; i++)
#pragma unroll
        for (int j = 0; j < 8; j++)
#pragma unroll
            for (int q = 0; q < 4; q++) acc[i][j][q] = 0.0f;

#define LOAD_STAGE(kt, s)                                                        \
    do {                                                                         \
        const __half* Ab_ = A + (size_t)bm * lda + (kt) * 32;                    \
        const uint32_t sa_ = sb + (uint32_t)(s) * STG_BYTES;                     \
        const uint32_t sbb_ = sa_ + AT_BYTES;                                    \
        _Pragma("unroll")                                                        \
        for (int i_ = 0; i_ < 4; i_++) {                                         \
            const int idx_ = tid + i_ * 128;                                     \
            const int r_ = idx_ >> 2, c_ = idx_ & 3;                             \
            cp16(sa_ + r_ * ASTRIDE + c_ * 16, Ab_ + (size_t)r_ * lda + c_ * 8); \
        }                                                                        \
        if (BNN) {                                                               \
            const __half* Bb_ = B + (size_t)(kt) * 32 * ldb + bn;                \
            _Pragma("unroll")                                                    \
            for (int i_ = 0; i_ < 4; i_++) {                                     \
                const int idx_ = tid + i_ * 128;                                 \
                const int r_ = idx_ >> 4, c_ = idx_ & 15;                        \
                cp16(sbb_ + r_ * BROWB_NN + c_ * 16,                             \
                     Bb_ + (size_t)r_ * ldb + c_ * 8);                           \
            }                                                                    \
        } else {                                                                 \
            const __half* Bb_ = B + (size_t)bn * ldb + (kt) * 32;                \
            _Pragma("unroll")                                                    \
            for (int i_ = 0; i_ < 4; i_++) {                                     \
                const int idx_ = tid + i_ * 128;                                 \
                const int r_ = idx_ >> 2, c_ = idx_ & 3;                         \
                cp16(sbb_ + r_ * ASTRIDE + c_ * 16,                              \
                     Bb_ + (size_t)r_ * ldb + c_ * 8);                           \
            }                                                                    \
        }                                                                        \
    } while (0)

    // prologue: fill STAGES-1 stages
#pragma unroll
    for (int s = 0; s < STAGES - 1; s++) {
        if (s < nch) LOAD_STAGE(s, s);
        CP_COMMIT();
    }

    int s_cur = 0;
    int s_load = STAGES - 1;

    for (int kt = 0; kt < nch; kt++) {
        CP_WAIT(STAGES - 2);
        __syncthreads();

        const int nk = kt + STAGES - 1;
        if (nk < nch) LOAD_STAGE(nk, s_load);
        CP_COMMIT();
        if (++s_load == STAGES) s_load = 0;

        const uint32_t sa  = sb + (uint32_t)s_cur * STG_BYTES;
        const uint32_t sbb = sa + AT_BYTES;
        if (++s_cur == STAGES) s_cur = 0;

        if (!dead) {
            uint32_t a[2][4][4], b[4][4];

            // a-frags for BOTH k16 steps
#pragma unroll
            for (int ks = 0; ks < 2; ks++)
#pragma unroll
                for (int mf = 0; mf < 4; mf++) {
                    const uint32_t addr = sa
                        + (m0 + mf * 16 + (lane & 15)) * ASTRIDE
                        + ks * 32 + ((lane >> 4) & 1) * 16;
                    LDSM4(a[ks][mf], addr);
                }
            // b-frags ks=0
#pragma unroll
            for (int nb = 0; nb < 4; nb++) {
                if (BNN) {
                    const uint32_t addr = sbb
                        + (lane & 15) * BROWB_NN
                        + (n0 + nb * 16 + ((lane >> 4) & 1) * 8) * 2;
                    LDSM4T(b[nb], addr);
                } else {
                    const uint32_t addr = sbb
                        + (n0 + nb * 16 + ((lane >> 4) & 1) * 8 + (lane & 7)) * ASTRIDE
                        + ((lane >> 3) & 1) * 16;
                    LDSM4(b[nb], addr);
                }
            }
            // MMA ks=0
#pragma unroll
            for (int mf = 0; mf < 4; mf++)
#pragma unroll
                for (int nf = 0; nf < 8; nf++)
                    MMA16816(acc[mf][nf], a[0][mf],
                             b[nf >> 1][(nf & 1) * 2],
                             b[nf >> 1][(nf & 1) * 2 + 1]);
            // b-frags ks=1 (WAR overlap with ks=0 MMAs)
#pragma unroll
            for (int nb = 0; nb < 4; nb++) {
                if (BNN) {
                    const uint32_t addr = sbb
                        + (16 + (lane & 15)) * BROWB_NN
                        + (n0 + nb * 16 + ((lane >> 4) & 1) * 8) * 2;
                    LDSM4T(b[nb], addr);
                } else {
                    const uint32_t addr = sbb
                        + (n0 + nb * 16 + ((lane >> 4) & 1) * 8 + (lane & 7)) * ASTRIDE
                        + 32 + ((lane >> 3) & 1) * 16;
                    LDSM4(b[nb], addr);
                }
            }
            // MMA ks=1
#pragma unroll
            for (int mf = 0; mf < 4; mf++)
#pragma unroll
                for (int nf = 0; nf < 8; nf++)
                    MMA16816(acc[mf][nf], a[1][mf],
                             b[nf >> 1][(nf & 1) * 2],
                             b[nf >> 1][(nf & 1) * 2 + 1]);
        }
    }

    // epilogue
    if (!dead) {
        const int gr = lane >> 2, gc = (lane & 3) * 2;
#pragma unroll
        for (int mf = 0; mf < 4; mf++) {
            const int row = bm + m0 + mf * 16 + gr;
#pragma unroll
            for (int nf = 0; nf < 8; nf++) {
                const int col = bn + n0 + nf * 8 + gc;
                const float v0 = acc[mf][nf][0] * scale;
                const float v1 = acc[mf][nf][1] * scale;
                const float v2 = acc[mf][nf][2] * scale;
                const float v3 = acc[mf][nf][3] * scale;
                if (OUTH) {
                    __half* Cp = (__half*)Cout + (long)bz * sC;
                    *(__half2*)(Cp + (size_t)row * ldc + col) =
                        __floats2half2_rn(v0, v1);
                    *(__half2*)(Cp + (size_t)(row + 8) * ldc + col) =
                        __floats2half2_rn(v2, v3);
                } else {
                    float* Cp = (float*)Cout + (long)bz * sC;
                    *(float2*)(Cp + (size_t)row * ldc + col) = make_float2(v0, v1);
                    *(float2*)(Cp + (size_t)(row + 8) * ldc + col) = make_float2(v2, v3);
                }
            }
        }
    }
#undef LOAD_STAGE
}

// ---- fp32 -> fp16 copy ---------------------------------------------------------
__global__ void cvt_half(const float* __restrict__ x, __half* __restrict__ xh, int n2)
{
    int i = blockIdx.x * blockDim.x + threadIdx.x;
    for (; i < n2; i += gridDim.x * blockDim.x) {
        float2 v = ((const float2*)x)[i];
        ((__half2*)xh)[i] = __floats2half2_rn(v.x, v.y);
    }
}

// ---- W^T (fp32 in, half out) ----------------------------------------------------
__global__ void transposeW(const float* __restrict__ W, __half* __restrict__ Wt)
{
    __shared__ float t[32][33];
    const int d0 = blockIdx.x * 32, c0 = blockIdx.y * 32;
    const int x = threadIdx.x, y = threadIdx.y;
#pragma unroll
    for (int i = 0; i < 32; i += 8)
        t[y + i][x] = W[(size_t)(c0 + y + i) * (3 * CC) + d0 + x];
    __syncthreads();
#pragma unroll
    for (int i = 0; i < 32; i += 8)
        Wt[(size_t)(d0 + y + i) * CC + c0 + x] = __float2half_rn(t[x][y + i]);
}

// ---- causal softmax: register-cached single pass. S half in, P half out. --------
__global__ void softmax_causal(const __half* __restrict__ S, __half* __restrict__ P)
{
    const int row = blockIdx.x;            // 0 .. B*T-1
    const int b = row / TT;
    const int i = row % TT;
    const __half* Srow = S + (size_t)b * TT * TT + (size_t)i * TT;
    __half* Prow = P + (size_t)b * TT * TT + (size_t)i * TT;
    const int len = i + 1;
    const int fillend = ((i >> 7) + 1) << 7;   // next 128 multiple
    const int t = threadIdx.x;

    __shared__ float sh[8];

    float r[8];
    int cnt = 0;
    float mx = -INFINITY;
#pragma unroll
    for (int q = 0; q < 8; q++) {
        const int j = t + q * 256;
        if (j < len) {
            r[q] = __half2float(Srow[j]);
            mx = fmaxf(mx, r[q]);
            cnt = q + 1;
        }
    }
#pragma unroll
    for (int o = 16; o; o >>= 1) mx = fmaxf(mx, __shfl_xor_sync(0xffffffffu, mx, o));
    if ((t & 31) == 0) sh[t >> 5] = mx;
    __syncthreads();
    mx = sh[0];
#pragma unroll
    for (int w = 1; w < 8; w++) mx = fmaxf(mx, sh[w]);
    __syncthreads();

    float sum = 0.0f;
#pragma unroll
    for (int q = 0; q < 8; q++) {
        if (q < cnt) {
            r[q] = __expf(r[q] - mx);
            sum += r[q];
        }
    }
#pragma unroll
    for (int o = 16; o; o >>= 1) sum += __shfl_xor_sync(0xffffffffu, sum, o);
    if ((t & 31) == 0) sh[t >> 5] = sum;
    __syncthreads();
    sum = sh[0];
#pragma unroll
    for (int w = 1; w < 8; w++) sum += sh[w];

    const float inv = 1.0f / sum;
#pragma unroll
    for (int q = 0; q < 8; q++) {
        const int j = t + q * 256;
        if (j < len) Prow[j] = __float2half_rn(r[q] * inv);
    }
    const __half hz = __float2half_rn(0.0f);
    for (int j = len + t; j < fillend; j += 256) Prow[j] = hz;
}

// ---- launch -----------------------------------------------------------------------
#define SMEM_NT (STAGES * (AT_BYTES + 128 * ASTRIDE))   // 102400
#define SMEM_NN (STAGES * (AT_BYTES + 32 * BROWB_NN))   // 94720

extern "C" void kernel_launch(void* const* d_in, const int* in_sizes, int n_in,
                              void* d_out, int out_size)
{
    const float* x = (const float*)d_in[0];   // [B,T,C]
    const float* W = (const float*)d_in[1];   // [C,3C]
    float* out = (float*)d_out;               // [B,T,C]

    __half *xh, *Wth, *qkvh, *Sh, *Ph;
    cudaGetSymbolAddress((void**)&xh,   g_xh);
    cudaGetSymbolAddress((void**)&Wth,  g_Wth);
    cudaGetSymbolAddress((void**)&qkvh, g_qkvh);
    cudaGetSymbolAddress((void**)&Sh,   g_Sh);
    cudaGetSymbolAddress((void**)&Ph,   g_Ph);

    cudaFuncSetAttribute(gemm_hmma<false, false, true, false>,
                         cudaFuncAttributeMaxDynamicSharedMemorySize, SMEM_NT);
    cudaFuncSetAttribute(gemm_hmma<true, false, true, false>,
                         cudaFuncAttributeMaxDynamicSharedMemorySize, SMEM_NT);
    cudaFuncSetAttribute(gemm_hmma<false, true, false, true>,
                         cudaFuncAttributeMaxDynamicSharedMemorySize, SMEM_NN);

    cudaStream_t st1;
    cudaStreamCreateWithFlags(&st1, cudaStreamNonBlocking);
    cudaEvent_t evFork, evW, evQK, evV;
    cudaEventCreateWithFlags(&evFork, cudaEventDisableTiming);
    cudaEventCreateWithFlags(&evW,    cudaEventDisableTiming);
    cudaEventCreateWithFlags(&evQK,   cudaEventDisableTiming);
    cudaEventCreateWithFlags(&evV,    cudaEventDisableTiming);

    // FORK st1 off the capture (origin) stream before any work lands on it.
    cudaEventRecord(evFork, 0);
    cudaStreamWaitEvent(st1, evFork, 0);

    // prep: cvt on origin, transposeW on st1 (overlap) — R11 schedule
    cvt_half<<<1024, 256>>>(x, xh, BB * TT * CC / 2);
    transposeW<<<dim3(3 * CC / 32, CC / 32), dim3(32, 8), 0, st1>>>(W, Wth);
    cudaEventRecord(evW, st1);

    // 1a) QK part of qkv: N = 2C (origin)
    cudaStreamWaitEvent(0, evW, 0);
    gemm_hmma<false, false, true, false>
        <<<dim3(2 * CC / 128, BB * TT / 128, 1), 128, SMEM_NT>>>(
        xh, Wth, qkvh, CC, CC, CC, 3 * CC, 0, 0, 0, 1.0f);
    cudaEventRecord(evQK, 0);

    // 1b) V part of qkv: N = C, on st1, after GEMM1qk (overlaps GEMM2+softmax)
    cudaStreamWaitEvent(st1, evQK, 0);
    gemm_hmma<false, false, true, false>
        <<<dim3(CC / 128, BB * TT / 128, 1), 128, SMEM_NT, st1>>>(
        xh, Wth + (size_t)2 * CC * CC, qkvh + 2 * CC,
        CC, CC, CC, 3 * CC, 0, 0, 0, 1.0f);
    cudaEventRecord(evV, st1);

    // 2) Sh = Q K^T / 32, all batches, triangular-compact, fp32 acc
    gemm_hmma<true, false, true, false>
        <<<dim3(136, 1, BB), 128, SMEM_NT>>>(
        qkvh, qkvh + CC, Sh, CC, 3 * CC, 3 * CC, TT,
        (long)TT * 3 * CC, (long)TT * 3 * CC, (long)TT * TT, 0.03125f);

    // 3) causal softmax -> Ph
    softmax_causal<<<BB * TT, 256>>>(Sh, Ph);

    // 4) out = P V (needs V): join st1, NN GEMM, heavy tiles first, fp32 acc
    cudaStreamWaitEvent(0, evV, 0);
    gemm_hmma<false, true, false, true>
        <<<dim3(CC / 128, TT / 128, BB), 128, SMEM_NN>>>(
        Ph, qkvh + 2 * CC, out, TT, TT, 3 * CC, CC,
        (long)TT * TT, (long)TT * 3 * CC, (long)TT * CC, 1.0f);

    cudaEventDestroy(evFork);
    cudaEventDestroy(evW);
    cudaEventDestroy(evQK);
    cudaEventDestroy(evV);
    cudaStreamDestroy(st1);
}

// round 15
// speedup vs baseline: 1.0631x; 1.0380x over previous
#include <cuda_runtime.h>
#include <cuda_fp16.h>
#include <math.h>
#include <stdint.h>

#define BB 4
#define TT 2048
#define CC 1024

// ---- scratch (static device globals; no allocs anywhere) --------------------
__device__ __align__(256) __half g_xh  [(size_t)BB * TT * CC];        // x in half
__device__ __align__(256) __half g_Wth [(size_t)3 * CC * CC];         // W^T [3C,C] half
__device__ __align__(256) __half g_qkvh[(size_t)BB * TT * 3 * CC];    // [B,T,3C] half
__device__ __align__(256) __half g_Sh  [(size_t)BB * TT * TT];        // scores half
__device__ __align__(256) __half g_Ph  [(size_t)BB * TT * TT];        // probs half

// ---- helpers ------------------------------------------------------------------
__device__ __forceinline__ uint32_t smem_u32(const void* p) {
    uint32_t a;
    asm("{ .reg .u64 t; cvta.to.shared.u64 t, %1; cvt.u32.u64 %0, t; }"
        : "=r"(a) : "l"(p));
    return a;
}
__device__ __forceinline__ void cp16(uint32_t dst, const void* src) {
    asm volatile("cp.async.cg.shared.global [%0], [%1], 16;"
                 :: "r"(dst), "l"(src) : "memory");
}
#define CP_COMMIT() asm volatile("cp.async.commit_group;" ::: "memory")
#define CP_WAIT(n)  asm volatile("cp.async.wait_group %0;" :: "n"(n) : "memory")

#define LDSM4(r, addr)                                                          \
    asm volatile("ldmatrix.sync.aligned.m8n8.x4.shared.b16 {%0,%1,%2,%3},[%4];" \
        : "=r"((r)[0]), "=r"((r)[1]), "=r"((r)[2]), "=r"((r)[3])                \
        : "r"(addr))

#define LDSM4T(r, addr)                                                         \
    asm volatile("ldmatrix.sync.aligned.m8n8.x4.trans.shared.b16 "              \
        "{%0,%1,%2,%3},[%4];"                                                   \
        : "=r"((r)[0]), "=r"((r)[1]), "=r"((r)[2]), "=r"((r)[3])                \
        : "r"(addr))

#define MMA16816(c, a, b0, b1)                                                  \
    asm volatile("mma.sync.aligned.m16n8k16.row.col.f32.f16.f16.f32 "           \
        "{%0,%1,%2,%3},{%4,%5,%6,%7},{%8,%9},{%0,%1,%2,%3};"                    \
        : "+f"((c)[0]), "+f"((c)[1]), "+f"((c)[2]), "+f"((c)[3])                 \
        : "r"((a)[0]), "r"((a)[1]), "r"((a)[2]), "r"((a)[3]),                    \
          "r"(b0), "r"(b1))

// ---- fp16 HMMA GEMM ------------------------------------------------------------
// BNN=false: C[M,N] = scale * A[M,K] * B[N,K]^T   (B row-major [N,K])
// BNN=true : C[M,N] = scale * A[M,K] * B[K,N]     (B row-major [K,N], ldmatrix.trans)
// TRI:  grid.x indexes the lower triangle of the (M/128 x M/128) tile grid.
// LIMK: truncate K at bm+128; blockIdx.y reversed so heavy tiles launch first.
// 128x128 CTA tile, BK=32, 5-stage cp.async, 128 thr = 4 warps (2x2 of 64x64).
#define STAGES     5
#define ASTRIDE    80                 // A smem row: 64B data + 16B pad
#define AT_BYTES   (128 * ASTRIDE)    // 10240
#define BROWB_NN   272                // NN B smem row: 256B data + 16B pad (odd/16)

template <bool TRI, bool LIMK, bool OUTH, bool BNN>
__global__ void __launch_bounds__(128, 2)
gemm_hmma(const __half* __restrict__ A, const __half* __restrict__ B,
          void* __restrict__ Cout,
          int K, int lda, int ldb, int ldc,
          long sA, long sB, long sC, float scale)
{
    constexpr uint32_t B_BYTES = BNN ? (32u * BROWB_NN) : (128u * ASTRIDE);
    constexpr uint32_t STG_BYTES = AT_BYTES + B_BYTES;

    extern __shared__ char smem[];
    const int bz = blockIdx.z;
    A += (long)bz * sA;
    B += (long)bz * sB;

    int bm, bn;
    if (TRI) {
        const int idx = blockIdx.x;
        int r = (int)((sqrtf(8.0f * idx + 1.0f) - 1.0f) * 0.5f);
        while ((r + 1) * (r + 2) / 2 <= idx) ++r;
        while (r * (r + 1) / 2 > idx) --r;
        bm = r * 128;
        bn = (idx - r * (r + 1) / 2) * 128;
    } else if (LIMK) {
        bm = (gridDim.y - 1 - blockIdx.y) * 128;   // heavy tiles first
        bn = blockIdx.x * 128;
    } else {
        bm = blockIdx.y * 128;
        bn = blockIdx.x * 128;
    }

    const int kend = LIMK ? min(K, bm + 128) : K;
    const int nch  = kend >> 5;                         // 32-K chunks

    const int tid = threadIdx.x, lane = tid & 31, wid = tid >> 5;
    const int m0 = (wid >> 1) * 64, n0 = (wid & 1) * 64;
    const uint32_t sb = smem_u32(smem);

    float acc[4][8][4];
#pragma unroll
    for (int i = 0; i < 4; i++)
#pragma unroll
        for (int j = 0; j < 8; j++)
#pragma unroll
            for (int q = 0; q < 4; q++) acc[i][j][q] = 0.0f;

#define LOAD_STAGE(kt, s)                                                        \
    do {                                                                         \
        const __half* Ab_ = A + (size_t)bm * lda + (kt) * 32;                    \
        const uint32_t sa_ = sb + (uint32_t)(s) * STG_BYTES;                     \
        const uint32_t sbb_ = sa_ + AT_BYTES;                                    \
        _Pragma("unroll")                                                        \
        for (int i_ = 0; i_ < 4; i_++) {                                         \
            const int idx_ = tid + i_ * 128;                                     \
            const int r_ = idx_ >> 2, c_ = idx_ & 3;                             \
            cp16(sa_ + r_ * ASTRIDE + c_ * 16, Ab_ + (size_t)r_ * lda + c_ * 8); \
        }                                                                        \
        if (BNN) {                                                               \
            const __half* Bb_ = B + (size_t)(kt) * 32 * ldb + bn;                \
            _Pragma("unroll")                                                    \
            for (int i_ = 0; i_ < 4; i_++) {                                     \
                const int idx_ = tid + i_ * 128;                                 \
                const int r_ = idx_ >> 4, c_ = idx_ & 15;                        \
                cp16(sbb_ + r_ * BROWB_NN + c_ * 16,                             \
                     Bb_ + (size_t)r_ * ldb + c_ * 8);                           \
            }                                                                    \
        } else {                                                                 \
            const __half* Bb_ = B + (size_t)bn * ldb + (kt) * 32;                \
            _Pragma("unroll")                                                    \
            for (int i_ = 0; i_ < 4; i_++) {                                     \
                const int idx_ = tid + i_ * 128;                                 \
                const int r_ = idx_ >> 2, c_ = idx_ & 3;                         \
                cp16(sbb_ + r_ * ASTRIDE + c_ * 16,                              \
                     Bb_ + (size_t)r_ * ldb + c_ * 8);                           \
            }                                                                    \
        }                                                                        \
    } while (0)

    // prologue: fill STAGES-1 stages
#pragma unroll
    for (int s = 0; s < STAGES - 1; s++) {
        if (s < nch) LOAD_STAGE(s, s);
        CP_COMMIT();
    }

    int s_cur = 0;
    int s_load = STAGES - 1;

    for (int kt = 0; kt < nch; kt++) {
        CP_WAIT(STAGES - 2);
        __syncthreads();

        const int nk = kt + STAGES - 1;
        if (nk < nch) LOAD_STAGE(nk, s_load);
        CP_COMMIT();
        if (++s_load == STAGES) s_load = 0;

        const uint32_t sa  = sb + (uint32_t)s_cur * STG_BYTES;
        const uint32_t sbb = sa + AT_BYTES;
        if (++s_cur == STAGES) s_cur = 0;

        uint32_t a[2][4][4], b[4][4];

        // a-frags for BOTH k16 steps
#pragma unroll
        for (int ks = 0; ks < 2; ks++)
#pragma unroll
            for (int mf = 0; mf < 4; mf++) {
                const uint32_t addr = sa
                    + (m0 + mf * 16 + (lane & 15)) * ASTRIDE
                    + ks * 32 + ((lane >> 4) & 1) * 16;
                LDSM4(a[ks][mf], addr);
            }
        // b-frags ks=0
#pragma unroll
        for (int nb = 0; nb < 4; nb++) {
            if (BNN) {
                const uint32_t addr = sbb
                    + (lane & 15) * BROWB_NN
                    + (n0 + nb * 16 + ((lane >> 4) & 1) * 8) * 2;
                LDSM4T(b[nb], addr);
            } else {
                const uint32_t addr = sbb
                    + (n0 + nb * 16 + ((lane >> 4) & 1) * 8 + (lane & 7)) * ASTRIDE
                    + ((lane >> 3) & 1) * 16;
                LDSM4(b[nb], addr);
            }
        }
        // MMA ks=0
#pragma unroll
        for (int mf = 0; mf < 4; mf++)
#pragma unroll
            for (int nf = 0; nf < 8; nf++)
                MMA16816(acc[mf][nf], a[0][mf],
                         b[nf >> 1][(nf & 1) * 2],
                         b[nf >> 1][(nf & 1) * 2 + 1]);
        // b-frags ks=1 (WAR overlap with ks=0 MMAs)
#pragma unroll
        for (int nb = 0; nb < 4; nb++) {
            if (BNN) {
                const uint32_t addr = sbb
                    + (16 + (lane & 15)) * BROWB_NN
                    + (n0 + nb * 16 + ((lane >> 4) & 1) * 8) * 2;
                LDSM4T(b[nb], addr);
            } else {
                const uint32_t addr = sbb
                    + (n0 + nb * 16 + ((lane >> 4) & 1) * 8 + (lane & 7)) * ASTRIDE
                    + 32 + ((lane >> 3) & 1) * 16;
                LDSM4(b[nb], addr);
            }
        }
        // MMA ks=1
#pragma unroll
        for (int mf = 0; mf < 4; mf++)
#pragma unroll
            for (int nf = 0; nf < 8; nf++)
                MMA16816(acc[mf][nf], a[1][mf],
                         b[nf >> 1][(nf & 1) * 2],
                         b[nf >> 1][(nf & 1) * 2 + 1]);
    }

    // epilogue
    const int gr = lane >> 2, gc = (lane & 3) * 2;
#pragma unroll
    for (int mf = 0; mf < 4; mf++) {
        const int row = bm + m0 + mf * 16 + gr;
#pragma unroll
        for (int nf = 0; nf < 8; nf++) {
            const int col = bn + n0 + nf * 8 + gc;
            const float v0 = acc[mf][nf][0] * scale;
            const float v1 = acc[mf][nf][1] * scale;
            const float v2 = acc[mf][nf][2] * scale;
            const float v3 = acc[mf][nf][3] * scale;
            if (OUTH) {
                __half* Cp = (__half*)Cout + (long)bz * sC;
                *(__half2*)(Cp + (size_t)row * ldc + col) =
                    __floats2half2_rn(v0, v1);
                *(__half2*)(Cp + (size_t)(row + 8) * ldc + col) =
                    __floats2half2_rn(v2, v3);
            } else {
                float* Cp = (float*)Cout + (long)bz * sC;
                *(float2*)(Cp + (size_t)row * ldc + col) = make_float2(v0, v1);
                *(float2*)(Cp + (size_t)(row + 8) * ldc + col) = make_float2(v2, v3);
            }
        }
    }
#undef LOAD_STAGE
}

// ---- fp32 -> fp16 copy, float4-vectorized ----------------------------------------
__global__ void cvt_half(const float* __restrict__ x, __half* __restrict__ xh, int n4)
{
    int i = blockIdx.x * blockDim.x + threadIdx.x;
    for (; i < n4; i += gridDim.x * blockDim.x) {
        float4 v = ((const float4*)x)[i];
        __half2 h0 = __floats2half2_rn(v.x, v.y);
        __half2 h1 = __floats2half2_rn(v.z, v.w);
        uint2 o;
        o.x = *(uint32_t*)&h0;
        o.y = *(uint32_t*)&h1;
        ((uint2*)xh)[i] = o;
    }
}

// ---- W^T (fp32 in, half out) ----------------------------------------------------
__global__ void transposeW(const float* __restrict__ W, __half* __restrict__ Wt)
{
    __shared__ float t[32][33];
    const int d0 = blockIdx.x * 32, c0 = blockIdx.y * 32;
    const int x = threadIdx.x, y = threadIdx.y;
#pragma unroll
    for (int i = 0; i < 32; i += 8)
        t[y + i][x] = W[(size_t)(c0 + y + i) * (3 * CC) + d0 + x];
    __syncthreads();
#pragma unroll
    for (int i = 0; i < 32; i += 8)
        Wt[(size_t)(d0 + y + i) * CC + c0 + x] = __float2half_rn(t[x][y + i]);
}

// ---- causal softmax: register-cached single pass. S half in, P half out. --------
__global__ void softmax_causal(const __half* __restrict__ S, __half* __restrict__ P)
{
    const int row = blockIdx.x;            // 0 .. B*T-1
    const int b = row / TT;
    const int i = row % TT;
    const __half* Srow = S + (size_t)b * TT * TT + (size_t)i * TT;
    __half* Prow = P + (size_t)b * TT * TT + (size_t)i * TT;
    const int len = i + 1;
    const int fillend = ((i >> 7) + 1) << 7;   // next 128 multiple
    const int t = threadIdx.x;

    __shared__ float sh[8];

    float r[8];
    int cnt = 0;
    float mx = -INFINITY;
#pragma unroll
    for (int q = 0; q < 8; q++) {
        const int j = t + q * 256;
        if (j < len) {
            r[q] = __half2float(Srow[j]);
            mx = fmaxf(mx, r[q]);
            cnt = q + 1;
        }
    }
#pragma unroll
    for (int o = 16; o; o >>= 1) mx = fmaxf(mx, __shfl_xor_sync(0xffffffffu, mx, o));
    if ((t & 31) == 0) sh[t >> 5] = mx;
    __syncthreads();
    mx = sh[0];
#pragma unroll
    for (int w = 1; w < 8; w++) mx = fmaxf(mx, sh[w]);
    __syncthreads();

    float sum = 0.0f;
#pragma unroll
    for (int q = 0; q < 8; q++) {
        if (q < cnt) {
            r[q] = __expf(r[q] - mx);
            sum += r[q];
        }
    }
#pragma unroll
    for (int o = 16; o; o >>= 1) sum += __shfl_xor_sync(0xffffffffu, sum, o);
    if ((t & 31) == 0) sh[t >> 5] = sum;
    __syncthreads();
    sum = sh[0];
#pragma unroll
    for (int w = 1; w < 8; w++) sum += sh[w];

    const float inv = 1.0f / sum;
#pragma unroll
    for (int q = 0; q < 8; q++) {
        const int j = t + q * 256;
        if (j < len) Prow[j] = __float2half_rn(r[q] * inv);
    }
    const __half hz = __float2half_rn(0.0f);
    for (int j = len + t; j < fillend; j += 256) Prow[j] = hz;
}

// ---- launch -----------------------------------------------------------------------
#define SMEM_NT (STAGES * (AT_BYTES + 128 * ASTRIDE))   // 102400
#define SMEM_NN (STAGES * (AT_BYTES + 32 * BROWB_NN))   // 94720

extern "C" void kernel_launch(void* const* d_in, const int* in_sizes, int n_in,
                              void* d_out, int out_size)
{
    const float* x = (const float*)d_in[0];   // [B,T,C]
    const float* W = (const float*)d_in[1];   // [C,3C]
    float* out = (float*)d_out;               // [B,T,C]

    __half *xh, *Wth, *qkvh, *Sh, *Ph;
    cudaGetSymbolAddress((void**)&xh,   g_xh);
    cudaGetSymbolAddress((void**)&Wth,  g_Wth);
    cudaGetSymbolAddress((void**)&qkvh, g_qkvh);
    cudaGetSymbolAddress((void**)&Sh,   g_Sh);
    cudaGetSymbolAddress((void**)&Ph,   g_Ph);

    cudaFuncSetAttribute(gemm_hmma<false, false, true, false>,
                         cudaFuncAttributeMaxDynamicSharedMemorySize, SMEM_NT);
    cudaFuncSetAttribute(gemm_hmma<true, false, true, false>,
                         cudaFuncAttributeMaxDynamicSharedMemorySize, SMEM_NT);
    cudaFuncSetAttribute(gemm_hmma<false, true, false, true>,
                         cudaFuncAttributeMaxDynamicSharedMemorySize, SMEM_NN);

    cudaStream_t st1;
    cudaStreamCreateWithFlags(&st1, cudaStreamNonBlocking);
    cudaEvent_t evFork, evW, evQK, evS, evV;
    cudaEventCreateWithFlags(&evFork, cudaEventDisableTiming);
    cudaEventCreateWithFlags(&evW,    cudaEventDisableTiming);
    cudaEventCreateWithFlags(&evQK,   cudaEventDisableTiming);
    cudaEventCreateWithFlags(&evS,    cudaEventDisableTiming);
    cudaEventCreateWithFlags(&evV,    cudaEventDisableTiming);

    // FORK st1 off the capture (origin) stream before any work lands on it.
    cudaEventRecord(evFork, 0);
    cudaStreamWaitEvent(st1, evFork, 0);

    // prep: cvt (float4) on origin, transposeW on st1
    cvt_half<<<1024, 256>>>(x, xh, BB * TT * CC / 4);
    transposeW<<<dim3(3 * CC / 32, CC / 32), dim3(32, 8), 0, st1>>>(W, Wth);
    cudaEventRecord(evW, st1);

    // 1a) QK part of qkv: N = 2C (origin)
    cudaStreamWaitEvent(0, evW, 0);
    gemm_hmma<false, false, true, false>
        <<<dim3(2 * CC / 128, BB * TT / 128, 1), 128, SMEM_NT>>>(
        xh, Wth, qkvh, CC, CC, CC, 3 * CC, 0, 0, 0, 1.0f);
    cudaEventRecord(evQK, 0);

    // 2) Sh = Q K^T / 32, all batches, triangular-compact (origin, exclusive
    //    tensor-pipe use — GEMM1v is deferred until this finishes)
    gemm_hmma<true, false, true, false>
        <<<dim3(136, 1, BB), 128, SMEM_NT>>>(
        qkvh, qkvh + CC, Sh, CC, 3 * CC, 3 * CC, TT,
        (long)TT * 3 * CC, (long)TT * 3 * CC, (long)TT * TT, 0.03125f);
    cudaEventRecord(evS, 0);

    // 1b) V part of qkv on st1, AFTER GEMM2 — its tensor work now runs
    //     exactly during softmax (hiding softmax's memory-bound 10us)
    cudaStreamWaitEvent(st1, evQK, 0);
    cudaStreamWaitEvent(st1, evS, 0);
    gemm_hmma<false, false, true, false>
        <<<dim3(CC / 128, BB * TT / 128, 1), 128, SMEM_NT, st1>>>(
        xh, Wth + (size_t)2 * CC * CC, qkvh + 2 * CC,
        CC, CC, CC, 3 * CC, 0, 0, 0, 1.0f);
    cudaEventRecord(evV, st1);

    // 3) causal softmax -> Ph (origin, concurrent with GEMM1v on st1)
    softmax_causal<<<BB * TT, 256>>>(Sh, Ph);

    // 4) out = P V: join st1 (V ready), NN GEMM, heavy tiles first
    cudaStreamWaitEvent(0, evV, 0);
    gemm_hmma<false, true, false, true>
        <<<dim3(CC / 128, TT / 128, BB), 128, SMEM_NN>>>(
        Ph, qkvh + 2 * CC, out, TT, TT, 3 * CC, CC,
        (long)TT * TT, (long)TT * 3 * CC, (long)TT * CC, 1.0f);

    cudaEventDestroy(evFork);
    cudaEventDestroy(evW);
    cudaEventDestroy(evQK);
    cudaEventDestroy(evS);
    cudaEventDestroy(evV);
    cudaStreamDestroy(st1);
}

// round 16
// speedup vs baseline: 1.0777x; 1.0137x over previous
#include <cuda_runtime.h>
#include <cuda_fp16.h>
#include <math.h>
#include <stdint.h>

#define BB 4
#define TT 2048
#define CC 1024

// ---- scratch (static device globals; no allocs anywhere) --------------------
__device__ __align__(256) __half g_xh  [(size_t)BB * TT * CC];        // x in half
__device__ __align__(256) __half g_Wth [(size_t)3 * CC * CC];         // W^T [3C,C] half
__device__ __align__(256) __half g_qkvh[(size_t)BB * TT * 3 * CC];    // [B,T,3C] half
__device__ __align__(256) __half g_Sh  [(size_t)BB * TT * TT];        // scores half
__device__ __align__(256) __half g_Ph  [(size_t)BB * TT * TT];        // probs half

// ---- helpers ------------------------------------------------------------------
__device__ __forceinline__ uint32_t smem_u32(const void* p) {
    uint32_t a;
    asm("{ .reg .u64 t; cvta.to.shared.u64 t, %1; cvt.u32.u64 %0, t; }"
        : "=r"(a) : "l"(p));
    return a;
}
__device__ __forceinline__ void cp16(uint32_t dst, const void* src) {
    asm volatile("cp.async.cg.shared.global [%0], [%1], 16;"
                 :: "r"(dst), "l"(src) : "memory");
}
#define CP_COMMIT() asm volatile("cp.async.commit_group;" ::: "memory")
#define CP_WAIT(n)  asm volatile("cp.async.wait_group %0;" :: "n"(n) : "memory")

#define LDSM4(r, addr)                                                          \
    asm volatile("ldmatrix.sync.aligned.m8n8.x4.shared.b16 {%0,%1,%2,%3},[%4];" \
        : "=r"((r)[0]), "=r"((r)[1]), "=r"((r)[2]), "=r"((r)[3])                \
        : "r"(addr))

#define LDSM4T(r, addr)                                                         \
    asm volatile("ldmatrix.sync.aligned.m8n8.x4.trans.shared.b16 "              \
        "{%0,%1,%2,%3},[%4];"                                                   \
        : "=r"((r)[0]), "=r"((r)[1]), "=r"((r)[2]), "=r"((r)[3])                \
        : "r"(addr))

#define MMA16816(c, a, b0, b1)                                                  \
    asm volatile("mma.sync.aligned.m16n8k16.row.col.f32.f16.f16.f32 "           \
        "{%0,%1,%2,%3},{%4,%5,%6,%7},{%8,%9},{%0,%1,%2,%3};"                    \
        : "+f"((c)[0]), "+f"((c)[1]), "+f"((c)[2]), "+f"((c)[3])                 \
        : "r"((a)[0]), "r"((a)[1]), "r"((a)[2]), "r"((a)[3]),                    \
          "r"(b0), "r"(b1))

// ---- fp16 HMMA GEMM ------------------------------------------------------------
// BNN=false: C[M,N] = scale * A[M,K] * B[N,K]^T   (B row-major [N,K])
// BNN=true : C[M,N] = scale * A[M,K] * B[K,N]     (B row-major [K,N], ldmatrix.trans)
// TRI:  grid.x indexes the lower triangle of the (M/128 x M/128) tile grid.
// LIMK: truncate K at bm+128; blockIdx.y reversed so heavy tiles launch first.
// 128x128 CTA tile, BK=32, 5-stage cp.async, 128 thr = 4 warps (2x2 of 64x64).
#define STAGES     5
#define ASTRIDE    80                 // A smem row: 64B data + 16B pad
#define AT_BYTES   (128 * ASTRIDE)    // 10240
#define BROWB_NN   272                // NN B smem row: 256B data + 16B pad (odd/16)

template <bool TRI, bool LIMK, bool OUTH, bool BNN>
__global__ void __launch_bounds__(128, 2)
gemm_hmma(const __half* __restrict__ A, const __half* __restrict__ B,
          void* __restrict__ Cout,
          int K, int lda, int ldb, int ldc,
          long sA, long sB, long sC, float scale)
{
    constexpr uint32_t B_BYTES = BNN ? (32u * BROWB_NN) : (128u * ASTRIDE);
    constexpr uint32_t STG_BYTES = AT_BYTES + B_BYTES;

    extern __shared__ char smem[];
    const int bz = blockIdx.z;
    A += (long)bz * sA;
    B += (long)bz * sB;

    int bm, bn;
    if (TRI) {
        const int idx = blockIdx.x;
        int r = (int)((sqrtf(8.0f * idx + 1.0f) - 1.0f) * 0.5f);
        while ((r + 1) * (r + 2) / 2 <= idx) ++r;
        while (r * (r + 1) / 2 > idx) --r;
        bm = r * 128;
        bn = (idx - r * (r + 1) / 2) * 128;
    } else if (LIMK) {
        bm = (gridDim.y - 1 - blockIdx.y) * 128;   // heavy tiles first
        bn = blockIdx.x * 128;
    } else {
        bm = blockIdx.y * 128;
        bn = blockIdx.x * 128;
    }

    const int kend = LIMK ? min(K, bm + 128) : K;
    const int nch  = kend >> 5;                         // 32-K chunks

    const int tid = threadIdx.x, lane = tid & 31, wid = tid >> 5;
    const int m0 = (wid >> 1) * 64, n0 = (wid & 1) * 64;
    const uint32_t sb = smem_u32(smem);

    float acc[4][8][4];
#pragma unroll
    for (int i = 0; i < 4; i++)
#pragma unroll
        for (int j = 0; j < 8; j++)
#pragma unroll
            for (int q = 0; q < 4; q++) acc[i][j][q] = 0.0f;

#define LOAD_STAGE(kt, s)                                                        \
    do {                                                                         \
        const __half* Ab_ = A + (size_t)bm * lda + (kt) * 32;                    \
        const uint32_t sa_ = sb + (uint32_t)(s) * STG_BYTES;                     \
        const uint32_t sbb_ = sa_ + AT_BYTES;                                    \
        _Pragma("unroll")                                                        \
        for (int i_ = 0; i_ < 4; i_++) {                                         \
            const int idx_ = tid + i_ * 128;                                     \
            const int r_ = idx_ >> 2, c_ = idx_ & 3;                             \
            cp16(sa_ + r_ * ASTRIDE + c_ * 16, Ab_ + (size_t)r_ * lda + c_ * 8); \
        }                                                                        \
        if (BNN) {                                                               \
            const __half* Bb_ = B + (size_t)(kt) * 32 * ldb + bn;                \
            _Pragma("unroll")                                                    \
            for (int i_ = 0; i_ < 4; i_++) {                                     \
                const int idx_ = tid + i_ * 128;                                 \
                const int r_ = idx_ >> 4, c_ = idx_ & 15;                        \
                cp16(sbb_ + r_ * BROWB_NN + c_ * 16,                             \
                     Bb_ + (size_t)r_ * ldb + c_ * 8);                           \
            }                                                                    \
        } else {                                                                 \
            const __half* Bb_ = B + (size_t)bn * ldb + (kt) * 32;                \
            _Pragma("unroll")                                                    \
            for (int i_ = 0; i_ < 4; i_++) {                                     \
                const int idx_ = tid + i_ * 128;                                 \
                const int r_ = idx_ >> 2, c_ = idx_ & 3;                         \
                cp16(sbb_ + r_ * ASTRIDE + c_ * 16,                              \
                     Bb_ + (size_t)r_ * ldb + c_ * 8);                           \
            }                                                                    \
        }                                                                        \
    } while (0)

    // prologue: fill STAGES-1 stages
#pragma unroll
    for (int s = 0; s < STAGES - 1; s++) {
        if (s < nch) LOAD_STAGE(s, s);
        CP_COMMIT();
    }

    int s_cur = 0;
    int s_load = STAGES - 1;

    for (int kt = 0; kt < nch; kt++) {
        CP_WAIT(STAGES - 2);
        __syncthreads();

        const int nk = kt + STAGES - 1;
        if (nk < nch) LOAD_STAGE(nk, s_load);
        CP_COMMIT();
        if (++s_load == STAGES) s_load = 0;

        const uint32_t sa  = sb + (uint32_t)s_cur * STG_BYTES;
        const uint32_t sbb = sa + AT_BYTES;
        if (++s_cur == STAGES) s_cur = 0;

        uint32_t a[2][4][4], b[4][4];

        // a-frags for BOTH k16 steps
#pragma unroll
        for (int ks = 0; ks < 2; ks++)
#pragma unroll
            for (int mf = 0; mf < 4; mf++) {
                const uint32_t addr = sa
                    + (m0 + mf * 16 + (lane & 15)) * ASTRIDE
                    + ks * 32 + ((lane >> 4) & 1) * 16;
                LDSM4(a[ks][mf], addr);
            }
        // b-frags ks=0
#pragma unroll
        for (int nb = 0; nb < 4; nb++) {
            if (BNN) {
                const uint32_t addr = sbb
                    + (lane & 15) * BROWB_NN
                    + (n0 + nb * 16 + ((lane >> 4) & 1) * 8) * 2;
                LDSM4T(b[nb], addr);
            } else {
                const uint32_t addr = sbb
                    + (n0 + nb * 16 + ((lane >> 4) & 1) * 8 + (lane & 7)) * ASTRIDE
                    + ((lane >> 3) & 1) * 16;
                LDSM4(b[nb], addr);
            }
        }
        // MMA ks=0
#pragma unroll
        for (int mf = 0; mf < 4; mf++)
#pragma unroll
            for (int nf = 0; nf < 8; nf++)
                MMA16816(acc[mf][nf], a[0][mf],
                         b[nf >> 1][(nf & 1) * 2],
                         b[nf >> 1][(nf & 1) * 2 + 1]);
        // b-frags ks=1 (WAR overlap with ks=0 MMAs)
#pragma unroll
        for (int nb = 0; nb < 4; nb++) {
            if (BNN) {
                const uint32_t addr = sbb
                    + (16 + (lane & 15)) * BROWB_NN
                    + (n0 + nb * 16 + ((lane >> 4) & 1) * 8) * 2;
                LDSM4T(b[nb], addr);
            } else {
                const uint32_t addr = sbb
                    + (n0 + nb * 16 + ((lane >> 4) & 1) * 8 + (lane & 7)) * ASTRIDE
                    + 32 + ((lane >> 3) & 1) * 16;
                LDSM4(b[nb], addr);
            }
        }
        // MMA ks=1
#pragma unroll
        for (int mf = 0; mf < 4; mf++)
#pragma unroll
            for (int nf = 0; nf < 8; nf++)
                MMA16816(acc[mf][nf], a[1][mf],
                         b[nf >> 1][(nf & 1) * 2],
                         b[nf >> 1][(nf & 1) * 2 + 1]);
    }

    // epilogue
    const int gr = lane >> 2, gc = (lane & 3) * 2;
#pragma unroll
    for (int mf = 0; mf < 4; mf++) {
        const int row = bm + m0 + mf * 16 + gr;
#pragma unroll
        for (int nf = 0; nf < 8; nf++) {
            const int col = bn + n0 + nf * 8 + gc;
            const float v0 = acc[mf][nf][0] * scale;
            const float v1 = acc[mf][nf][1] * scale;
            const float v2 = acc[mf][nf][2] * scale;
            const float v3 = acc[mf][nf][3] * scale;
            if (OUTH) {
                __half* Cp = (__half*)Cout + (long)bz * sC;
                *(__half2*)(Cp + (size_t)row * ldc + col) =
                    __floats2half2_rn(v0, v1);
                *(__half2*)(Cp + (size_t)(row + 8) * ldc + col) =
                    __floats2half2_rn(v2, v3);
            } else {
                float* Cp = (float*)Cout + (long)bz * sC;
                *(float2*)(Cp + (size_t)row * ldc + col) = make_float2(v0, v1);
                *(float2*)(Cp + (size_t)(row + 8) * ldc + col) = make_float2(v2, v3);
            }
        }
    }
#undef LOAD_STAGE
}

// ---- fused prep: x->half (float4) + W^T (fp32 in, half out), one launch ----------
// blocks [0, CVT_BLKS): grid-stride convert; blocks [CVT_BLKS, ...): 32x32 W tiles.
#define CVT_BLKS 1024
#define WT_BX    (3 * CC / 32)   // 96
#define WT_BY    (CC / 32)       // 32

__global__ void prep(const float* __restrict__ x, __half* __restrict__ xh, int n4,
                     const float* __restrict__ W, __half* __restrict__ Wt)
{
    __shared__ float t[32][33];
    const int tid = threadIdx.x;

    if (blockIdx.x < CVT_BLKS) {
        int i = blockIdx.x * 256 + tid;
        for (; i < n4; i += CVT_BLKS * 256) {
            float4 v = ((const float4*)x)[i];
            __half2 h0 = __floats2half2_rn(v.x, v.y);
            __half2 h1 = __floats2half2_rn(v.z, v.w);
            uint2 o;
            o.x = *(uint32_t*)&h0;
            o.y = *(uint32_t*)&h1;
            ((uint2*)xh)[i] = o;
        }
    } else {
        const int b = blockIdx.x - CVT_BLKS;
        const int d0 = (b % WT_BX) * 32, c0 = (b / WT_BX) * 32;
        const int xx = tid & 31, yy = tid >> 5;   // 32x8
#pragma unroll
        for (int i = 0; i < 32; i += 8)
            t[yy + i][xx] = W[(size_t)(c0 + yy + i) * (3 * CC) + d0 + xx];
        __syncthreads();
#pragma unroll
        for (int i = 0; i < 32; i += 8)
            Wt[(size_t)(d0 + yy + i) * CC + c0 + xx] = __float2half_rn(t[xx][yy + i]);
    }
}

// ---- causal softmax: register-cached single pass. S half in, P half out. --------
__global__ void softmax_causal(const __half* __restrict__ S, __half* __restrict__ P)
{
    const int row = blockIdx.x;            // 0 .. B*T-1
    const int b = row / TT;
    const int i = row % TT;
    const __half* Srow = S + (size_t)b * TT * TT + (size_t)i * TT;
    __half* Prow = P + (size_t)b * TT * TT + (size_t)i * TT;
    const int len = i + 1;
    const int fillend = ((i >> 7) + 1) << 7;   // next 128 multiple
    const int t = threadIdx.x;

    __shared__ float sh[8];

    float r[8];
    int cnt = 0;
    float mx = -INFINITY;
#pragma unroll
    for (int q = 0; q < 8; q++) {
        const int j = t + q * 256;
        if (j < len) {
            r[q] = __half2float(Srow[j]);
            mx = fmaxf(mx, r[q]);
            cnt = q + 1;
        }
    }
#pragma unroll
    for (int o = 16; o; o >>= 1) mx = fmaxf(mx, __shfl_xor_sync(0xffffffffu, mx, o));
    if ((t & 31) == 0) sh[t >> 5] = mx;
    __syncthreads();
    mx = sh[0];
#pragma unroll
    for (int w = 1; w < 8; w++) mx = fmaxf(mx, sh[w]);
    __syncthreads();

    float sum = 0.0f;
#pragma unroll
    for (int q = 0; q < 8; q++) {
        if (q < cnt) {
            r[q] = __expf(r[q] - mx);
            sum += r[q];
        }
    }
#pragma unroll
    for (int o = 16; o; o >>= 1) sum += __shfl_xor_sync(0xffffffffu, sum, o);
    if ((t & 31) == 0) sh[t >> 5] = sum;
    __syncthreads();
    sum = sh[0];
#pragma unroll
    for (int w = 1; w < 8; w++) sum += sh[w];

    const float inv = 1.0f / sum;
#pragma unroll
    for (int q = 0; q < 8; q++) {
        const int j = t + q * 256;
        if (j < len) Prow[j] = __float2half_rn(r[q] * inv);
    }
    const __half hz = __float2half_rn(0.0f);
    for (int j = len + t; j < fillend; j += 256) Prow[j] = hz;
}

// ---- launch -----------------------------------------------------------------------
#define SMEM_NT (STAGES * (AT_BYTES + 128 * ASTRIDE))   // 102400
#define SMEM_NN (STAGES * (AT_BYTES + 32 * BROWB_NN))   // 94720

extern "C" void kernel_launch(void* const* d_in, const int* in_sizes, int n_in,
                              void* d_out, int out_size)
{
    const float* x = (const float*)d_in[0];   // [B,T,C]
    const float* W = (const float*)d_in[1];   // [C,3C]
    float* out = (float*)d_out;               // [B,T,C]

    __half *xh, *Wth, *qkvh, *Sh, *Ph;
    cudaGetSymbolAddress((void**)&xh,   g_xh);
    cudaGetSymbolAddress((void**)&Wth,  g_Wth);
    cudaGetSymbolAddress((void**)&qkvh, g_qkvh);
    cudaGetSymbolAddress((void**)&Sh,   g_Sh);
    cudaGetSymbolAddress((void**)&Ph,   g_Ph);

    cudaFuncSetAttribute(gemm_hmma<false, false, true, false>,
                         cudaFuncAttributeMaxDynamicSharedMemorySize, SMEM_NT);
    cudaFuncSetAttribute(gemm_hmma<true, false, true, false>,
                         cudaFuncAttributeMaxDynamicSharedMemorySize, SMEM_NT);
    cudaFuncSetAttribute(gemm_hmma<false, true, false, true>,
                         cudaFuncAttributeMaxDynamicSharedMemorySize, SMEM_NN);

    cudaStream_t st1;
    cudaStreamCreateWithFlags(&st1, cudaStreamNonBlocking);
    cudaEvent_t evFork, evS, evV;
    cudaEventCreateWithFlags(&evFork, cudaEventDisableTiming);
    cudaEventCreateWithFlags(&evS,    cudaEventDisableTiming);
    cudaEventCreateWithFlags(&evV,    cudaEventDisableTiming);

    // FORK st1 off the capture (origin) stream before any work lands on it.
    cudaEventRecord(evFork, 0);
    cudaStreamWaitEvent(st1, evFork, 0);

    // 0) fused prep: x->half + W^T, one launch on origin (no cross-stream wait)
    prep<<<CVT_BLKS + WT_BX * WT_BY, 256>>>(x, xh, BB * TT * CC / 4, W, Wth);

    // 1a) QK part of qkv: N = 2C (origin, directly after prep)
    gemm_hmma<false, false, true, false>
        <<<dim3(2 * CC / 128, BB * TT / 128, 1), 128, SMEM_NT>>>(
        xh, Wth, qkvh, CC, CC, CC, 3 * CC, 0, 0, 0, 1.0f);

    // 2) Sh = Q K^T / 32, all batches, triangular-compact (origin, exclusive
    //    tensor-pipe use — GEMM1v deferred until this finishes)
    gemm_hmma<true, false, true, false>
        <<<dim3(136, 1, BB), 128, SMEM_NT>>>(
        qkvh, qkvh + CC, Sh, CC, 3 * CC, 3 * CC, TT,
        (long)TT * 3 * CC, (long)TT * 3 * CC, (long)TT * TT, 0.03125f);
    cudaEventRecord(evS, 0);

    // 1b) V part of qkv on st1, AFTER GEMM2 — runs exactly during softmax
    cudaStreamWaitEvent(st1, evS, 0);
    gemm_hmma<false, false, true, false>
        <<<dim3(CC / 128, BB * TT / 128, 1), 128, SMEM_NT, st1>>>(
        xh, Wth + (size_t)2 * CC * CC, qkvh + 2 * CC,
        CC, CC, CC, 3 * CC, 0, 0, 0, 1.0f);
    cudaEventRecord(evV, st1);

    // 3) causal softmax -> Ph (origin, concurrent with GEMM1v on st1)
    softmax_causal<<<BB * TT, 256>>>(Sh, Ph);

    // 4) out = P V: join st1 (V ready), NN GEMM, heavy tiles first
    cudaStreamWaitEvent(0, evV, 0);
    gemm_hmma<false, true, false, true>
        <<<dim3(CC / 128, TT / 128, BB), 128, SMEM_NN>>>(
        Ph, qkvh + 2 * CC, out, TT, TT, 3 * CC, CC,
        (long)TT * TT, (long)TT * 3 * CC, (long)TT * CC, 1.0f);

    cudaEventDestroy(evFork);
    cudaEventDestroy(evS);
    cudaEventDestroy(evV);
    cudaStreamDestroy(st1);
}